// round 11
// baseline (speedup 1.0000x reference)
#include <cuda_runtime.h>
#include <cuda_fp16.h>
#include <math.h>
#include <float.h>
#include <stdint.h>

#define B_      2
#define N_KP    256
#define C_      256
#define HF_     64
#define WF_     64
#define ROI_    15
#define P2_     225
#define HID_    256
#define HEADS_  8
#define DH_     32
#define DEPTH_  3
#define FFN_    1024
#define NQ_     16
#define BN_     512          // B_*N_KP
#define MROWS_  8192         // BN_*NQ_
#define MMEM_   115200       // BN_*P2_
#define SPAD_   240          // padded S row; cols 225..239 zeroed
#define LN_EPS_ 1e-5f

#define STG_HALVES_ 5120
#define GEMM_SMEM_  (3 * 2 * STG_HALVES_ * 2)    // 61440 B

// ---------------- scratch ----------------
__device__ float g_imgT[(size_t)B_ * HF_ * WF_ * C_];
__device__ float g_tgt [(size_t)MROWS_ * HID_];
__device__ float g_y   [(size_t)MROWS_ * HID_];
__device__ unsigned char g_valid[BN_];

// fp16 activations
__device__ __half g_feat_h[(size_t)MMEM_ * C_];
__device__ __half g_mem_h [(size_t)MMEM_ * C_];
__device__ __half g_tgt_h [(size_t)MROWS_ * HID_];
__device__ __half g_ctx_h [(size_t)MROWS_ * HID_];
__device__ __half g_qkv_h [(size_t)MROWS_ * 3 * HID_];
__device__ __half g_qc_h  [(size_t)MROWS_ * HID_];
__device__ __half g_uh    [(size_t)BN_ * 128 * HID_];  // U, then T
__device__ __half g_sh    [(size_t)BN_ * 128 * SPAD_];
__device__ __half g_ffn_h [(size_t)MROWS_ * FFN_];
// fp16 weights
__device__ __half g_projw_h[65536];
__device__ __half g_sqkv_h [3 * 3 * 65536];
__device__ __half g_sout_h [3 * 65536];
__device__ __half g_cqkv_h [3 * 3 * 65536];
__device__ __half g_cout_h [3 * 65536];
__device__ __half g_f1_h   [3 * 262144];
__device__ __half g_f2_h   [3 * 262144];

// ---------------- helpers ----------------
__device__ __forceinline__ void mma_f16(float* c, const uint32_t* a, const uint32_t* b) {
    asm volatile(
        "mma.sync.aligned.m16n8k16.row.col.f32.f16.f16.f32 "
        "{%0,%1,%2,%3}, {%4,%5,%6,%7}, {%8,%9}, {%0,%1,%2,%3};\n"
        : "+f"(c[0]), "+f"(c[1]), "+f"(c[2]), "+f"(c[3])
        : "r"(a[0]), "r"(a[1]), "r"(a[2]), "r"(a[3]), "r"(b[0]), "r"(b[1]));
}

__device__ __forceinline__ void ldsm4(uint32_t* r, uint32_t saddr) {
    asm volatile("ldmatrix.sync.aligned.m8n8.x4.shared.b16 {%0,%1,%2,%3}, [%4];\n"
                 : "=r"(r[0]), "=r"(r[1]), "=r"(r[2]), "=r"(r[3]) : "r"(saddr));
}
__device__ __forceinline__ void ldsm4t(uint32_t* r, uint32_t saddr) {
    asm volatile("ldmatrix.sync.aligned.m8n8.x4.trans.shared.b16 {%0,%1,%2,%3}, [%4];\n"
                 : "=r"(r[0]), "=r"(r[1]), "=r"(r[2]), "=r"(r[3]) : "r"(saddr));
}

__device__ __forceinline__ void cpa16(void* smem_ptr, const void* gptr, bool pred) {
    uint32_t sa = (uint32_t)__cvta_generic_to_shared(smem_ptr);
    int sz = pred ? 16 : 0;
    asm volatile("cp.async.cg.shared.global [%0], [%1], 16, %2;\n"
                 :: "r"(sa), "l"(gptr), "r"(sz));
}
#define CPA_COMMIT() asm volatile("cp.async.commit_group;\n")
#define CPA_WAIT(n)  asm volatile("cp.async.wait_group %0;\n" :: "n"(n))

// ---------------- fused weight convert ----------------
#define W0_ 65536      // proj
#define W1_ 589824     // self_qkv
#define W2_ 196608     // self_out
#define W3_ 589824     // cross_qkv
#define W4_ 196608     // cross_out
#define W5_ 786432     // ffn1
#define W6_ 786432     // ffn2
#define WT_ (W0_+W1_+W2_+W3_+W4_+W5_+W6_)   // 3211264

__global__ void f2h_all(const float* __restrict__ p0, const float* __restrict__ p1,
                        const float* __restrict__ p2, const float* __restrict__ p3,
                        const float* __restrict__ p4, const float* __restrict__ p5,
                        const float* __restrict__ p6) {
    long i = (long)blockIdx.x * 256 + threadIdx.x;
    if (i >= WT_) return;
    long o = i;
    if (o < W0_) { g_projw_h[o] = __float2half_rn(p0[o]); return; } o -= W0_;
    if (o < W1_) { g_sqkv_h[o]  = __float2half_rn(p1[o]); return; } o -= W1_;
    if (o < W2_) { g_sout_h[o]  = __float2half_rn(p2[o]); return; } o -= W2_;
    if (o < W3_) { g_cqkv_h[o]  = __float2half_rn(p3[o]); return; } o -= W3_;
    if (o < W4_) { g_cout_h[o]  = __float2half_rn(p4[o]); return; } o -= W4_;
    if (o < W5_) { g_f1_h[o]    = __float2half_rn(p5[o]); return; } o -= W5_;
    g_f2_h[o] = __float2half_rn(p6[o]);
}

__global__ void decode_mask(const unsigned char* __restrict__ m, unsigned char* __restrict__ out) {
    __shared__ int flag;
    if (threadIdx.x == 0) flag = 0;
    __syncthreads();
    int i = threadIdx.x;
    unsigned char v8 = m[i];
    if ((i & 3) != 0 && v8 != 0) atomicOr(&flag, 1);
    __syncthreads();
    if (flag) out[i] = (v8 != 0);
    else      out[i] = (((const int*)m)[i] != 0);
}

__global__ void transpose_img(const float* __restrict__ img) {
    int x = blockIdx.x, y = blockIdx.y, b = blockIdx.z, c = threadIdx.x;
    g_imgT[(((size_t)b * HF_ + y) * WF_ + x) * C_ + c] =
        img[(((size_t)b * C_ + c) * HF_ + y) * WF_ + x];
}

// ---------------- ROI bilinear gather -> fp16 feat ----------------
__global__ __launch_bounds__(256) void roi_gather(const float* __restrict__ kp) {
    int p = blockIdx.x, n = blockIdx.y, b = blockIdx.z, c = threadIdx.x;
    int iy = p / ROI_, ix = p % ROI_;
    float rc0 = rintf(kp[((size_t)b * N_KP + n) * 2 + 0]);
    float rc1 = rintf(kp[((size_t)b * N_KP + n) * 2 + 1]);
    float gy = rc0 + (float)(iy - 7);
    float gx = rc1 + (float)(ix - 7);
    float gxn = __fdiv_rn(gx, 511.0f) * 2.0f - 1.0f;
    float gyn = __fdiv_rn(gy, 511.0f) * 2.0f - 1.0f;
    bool invalid = (gxn < -1.0f) || (gyn < -1.0f) || (gxn > 1.0f) || (gyn > 1.0f);
    __half* dst = g_feat_h + ((size_t)((b * N_KP + n) * P2_ + p)) * C_;
    if (invalid) { dst[c] = __float2half_rn(0.0f); return; }
    float x = ((gxn + 1.0f) * (float)WF_ - 1.0f) * 0.5f;
    float y = ((gyn + 1.0f) * (float)HF_ - 1.0f) * 0.5f;
    float x0f = floorf(x), y0f = floorf(y);
    float wx = x - x0f, wy = y - y0f;
    int x0 = (int)x0f, y0 = (int)y0f;
    int x1 = x0 + 1, y1 = y0 + 1;
    float w00 = (1.0f - wy) * (1.0f - wx);
    float w01 = (1.0f - wy) * wx;
    float w10 = wy * (1.0f - wx);
    float w11 = wy * wx;
    float acc = 0.0f;
    if (y0 >= 0 && y0 < HF_) {
        const float* rowp = g_imgT + ((size_t)(b * HF_ + y0) * WF_) * C_;
        if (x0 >= 0 && x0 < WF_) acc += w00 * rowp[(size_t)x0 * C_ + c];
        if (x1 >= 0 && x1 < WF_) acc += w01 * rowp[(size_t)x1 * C_ + c];
    }
    if (y1 >= 0 && y1 < HF_) {
        const float* rowp = g_imgT + ((size_t)(b * HF_ + y1) * WF_) * C_;
        if (x0 >= 0 && x0 < WF_) acc += w10 * rowp[(size_t)x0 * C_ + c];
        if (x1 >= 0 && x1 < WF_) acc += w11 * rowp[(size_t)x1 * C_ + c];
    }
    dst[c] = __float2half_rn(acc);
}

// ================= fp16 GEMM (ldmatrix + 3-stage cp.async, K-tile 32) =================
template<bool TB, bool HAS_BIAS, bool HAS_RES, bool RELU, bool OUT16>
__global__ __launch_bounds__(256, 2) void gemm_h(
    const __half* __restrict__ A, const __half* __restrict__ B,
    const float* __restrict__ bias, const float* __restrict__ Res,
    void* __restrict__ Cv,
    int M, int N, int K, int lda, int ldb, int ldc,
    long long sA, long long sB, long long sC, float alpha)
{
    extern __shared__ __half hsm[];
    __half* Asm = hsm;
    __half* Bsm = hsm + 3 * STG_HALVES_;

    long long z = blockIdx.z;
    A += z * sA; B += z * sB;
    float* Cf = (float*)Cv + (OUT16 ? 0 : z * sC);
    __half* Ch = (__half*)Cv + (OUT16 ? z * sC : 0);
    if (HAS_RES) Res += z * sC;

    int m0 = blockIdx.y * 128, n0 = blockIdx.x * 128;
    int t = threadIdx.x;
    int wid = t >> 5, lane = t & 31;
    int warp_m = wid >> 2;
    int warp_n = wid & 3;

    int l7 = lane & 7;
    int gidx = lane >> 3;

    uint32_t As_u = (uint32_t)__cvta_generic_to_shared(Asm);
    uint32_t Bs_u = (uint32_t)__cvta_generic_to_shared(Bsm);
    uint32_t a_lane  = (uint32_t)(((l7 + (gidx & 1) * 8) * 40 + (gidx >> 1) * 8) * 2);
    uint32_t bt_lane = a_lane;
    uint32_t bn_lane = (uint32_t)(((l7 + (gidx >> 1) * 8) * 136 + (gidx & 1) * 8) * 2);

    float acc[4][4][4];
#pragma unroll
    for (int i = 0; i < 4; i++)
#pragma unroll
        for (int j = 0; j < 4; j++)
#pragma unroll
            for (int r = 0; r < 4; r++) acc[i][j][r] = 0.0f;

    int KT = (K + 31) >> 5;

    auto load_tile = [&](int st, int k0) {
#pragma unroll
        for (int i = 0; i < 2; i++) {
            int lin = t + i * 256;
            int row = lin >> 2;
            int kc  = (lin & 3) * 8;
            int gm = m0 + row, gk = k0 + kc;
            cpa16(&Asm[st * STG_HALVES_ + row * 40 + kc],
                  A + (size_t)gm * lda + gk, gm < M && gk < K);
        }
        if (TB) {
#pragma unroll
            for (int i = 0; i < 2; i++) {
                int lin = t + i * 256;
                int row = lin >> 2;
                int kc  = (lin & 3) * 8;
                int gn = n0 + row, gk = k0 + kc;
                cpa16(&Bsm[st * STG_HALVES_ + row * 40 + kc],
                      B + (size_t)gn * ldb + gk, gn < N && gk < K);
            }
        } else {
#pragma unroll
            for (int i = 0; i < 2; i++) {
                int lin = t + i * 256;
                int kk = lin >> 4;
                int nc = (lin & 15) * 8;
                int gk = k0 + kk;
                cpa16(&Bsm[st * STG_HALVES_ + kk * 136 + nc],
                      B + (size_t)gk * ldb + n0 + nc, gk < K);
            }
        }
    };

    load_tile(0, 0); CPA_COMMIT();
    if (1 < KT) { load_tile(1, 32); CPA_COMMIT(); }

    for (int kt = 0; kt < KT; kt++) {
        if (kt + 1 < KT) { CPA_WAIT(1); } else { CPA_WAIT(0); }
        __syncthreads();
        if (kt + 2 < KT) { load_tile((kt + 2) % 3, (kt + 2) * 32); CPA_COMMIT(); }

        int st = kt % 3;
        uint32_t stoff = (uint32_t)(st * STG_HALVES_ * 2);
#pragma unroll
        for (int ks = 0; ks < 32; ks += 16) {
            uint32_t af[4][4];
#pragma unroll
            for (int mt = 0; mt < 4; mt++)
                ldsm4(af[mt], As_u + stoff +
                      (uint32_t)(((warp_m * 64 + mt * 16) * 40 + ks) * 2) + a_lane);
            uint32_t bf[4][2];
#pragma unroll
            for (int np = 0; np < 2; np++) {
                uint32_t tmp[4];
                if (TB) {
                    ldsm4(tmp, Bs_u + stoff +
                          (uint32_t)(((warp_n * 32 + np * 16) * 40 + ks) * 2) + bt_lane);
                } else {
                    ldsm4t(tmp, Bs_u + stoff +
                           (uint32_t)((ks * 136 + warp_n * 32 + np * 16) * 2) + bn_lane);
                }
                bf[2 * np][0]     = tmp[0]; bf[2 * np][1]     = tmp[2];
                bf[2 * np + 1][0] = tmp[1]; bf[2 * np + 1][1] = tmp[3];
            }
#pragma unroll
            for (int mt = 0; mt < 4; mt++)
#pragma unroll
                for (int nt = 0; nt < 4; nt++)
                    mma_f16(acc[mt][nt], af[mt], bf[nt]);
        }
    }

    // ---- epilogue ----
    int gq = lane >> 2, tq2 = lane & 3;
#pragma unroll
    for (int mt = 0; mt < 4; mt++) {
        int row0 = m0 + warp_m * 64 + mt * 16 + gq;
#pragma unroll
        for (int nt = 0; nt < 4; nt++) {
            int col = n0 + warp_n * 32 + nt * 8 + tq2 * 2;
#pragma unroll
            for (int half = 0; half < 2; half++) {
                int row = row0 + half * 8;
                if (row >= M) continue;
#pragma unroll
                for (int e = 0; e < 2; e++) {
                    int cc = col + e;
                    if (cc >= N) continue;
                    float v = acc[mt][nt][half * 2 + e] * alpha;
                    if (HAS_BIAS) v += bias[cc];
                    if (HAS_RES)  v += Res[(size_t)row * ldc + cc];
                    if (RELU)     v = fmaxf(v, 0.0f);
                    if (OUT16) Ch[(size_t)row * ldc + cc] = __float2half_rn(v);
                    else       Cf[(size_t)row * ldc + cc] = v;
                }
            }
        }
    }
}

// ---------------- tgt init ----------------
__global__ void init_tgt(const float* __restrict__ qe) {
    size_t i = (size_t)blockIdx.x * 256 + threadIdx.x;
    int c = (int)(i & 255);
    int q = (int)((i >> 8) & 15);
    float v = qe[q * HID_ + c];
    g_tgt[i] = v;
    g_tgt_h[i] = __float2half_rn(v);
}

// ---------------- self attention (fp16 qkv in, fp16 ctx out) ----------------
__global__ __launch_bounds__(256) void self_attn() {
    int bn = blockIdx.x;
    __shared__ float sq[NQ_][260];
    __shared__ float sk[NQ_][260];
    __shared__ float sa[HEADS_][NQ_][NQ_ + 1];
    int t = threadIdx.x;
    const __half* base = g_qkv_h + (size_t)bn * NQ_ * 768;
    for (int i = t; i < NQ_ * HID_; i += 256) {
        int q = i >> 8, c = i & 255;
        sq[q][c] = __half2float(base[q * 768 + c]);
        sk[q][c] = __half2float(base[q * 768 + 256 + c]);
    }
    __syncthreads();
    const float scale = 0.17677669529663687f;
    for (int i = t; i < HEADS_ * NQ_ * NQ_; i += 256) {
        int h = i >> 8, q = (i >> 4) & 15, kk = i & 15;
        float acc = 0.0f;
#pragma unroll
        for (int d = 0; d < DH_; d++) acc += sq[q][h * DH_ + d] * sk[kk][h * DH_ + d];
        sa[h][q][kk] = acc * scale;
    }
    __syncthreads();
    if (t < HEADS_ * NQ_) {
        int h = t >> 4, q = t & 15;
        float m = -FLT_MAX;
#pragma unroll
        for (int kk = 0; kk < NQ_; kk++) m = fmaxf(m, sa[h][q][kk]);
        float s = 0.0f;
#pragma unroll
        for (int kk = 0; kk < NQ_; kk++) { float e = expf(sa[h][q][kk] - m); sa[h][q][kk] = e; s += e; }
        float inv = 1.0f / s;
#pragma unroll
        for (int kk = 0; kk < NQ_; kk++) sa[h][q][kk] *= inv;
    }
    __syncthreads();
    __half* out = g_ctx_h + (size_t)bn * NQ_ * HID_;
    for (int i = t; i < NQ_ * HID_; i += 256) {
        int q = i >> 8, c = i & 255;
        int h = c >> 5;
        float acc = 0.0f;
#pragma unroll
        for (int kk = 0; kk < NQ_; kk++)
            acc += sa[h][q][kk] * __half2float(base[kk * 768 + 512 + c]);
        out[q * HID_ + c] = __float2half_rn(acc);
    }
}

// ---------------- cross-attn U = Q_h @ Wk_h ----------------
__global__ __launch_bounds__(256) void cross_u(const float* __restrict__ Wk) {
    int h = blockIdx.x, bn = blockIdx.y;
    int c = threadIdx.x;
    __shared__ float sq[NQ_][DH_];
    for (int i = threadIdx.x; i < NQ_ * DH_; i += 256) {
        int q = i >> 5, d = i & 31;
        sq[q][d] = __half2float(g_qc_h[((size_t)bn * NQ_ + q) * HID_ + h * DH_ + d]);
    }
    __syncthreads();
    float acc[NQ_] = {};
#pragma unroll 4
    for (int d = 0; d < DH_; d++) {
        float w = Wk[(size_t)(h * DH_ + d) * HID_ + c];
#pragma unroll
        for (int q = 0; q < NQ_; q++) acc[q] += sq[q][d] * w;
    }
    __half* dst = g_uh + ((size_t)bn * 128 + h * NQ_) * HID_ + c;
#pragma unroll
    for (int q = 0; q < NQ_; q++) dst[(size_t)q * HID_] = __float2half_rn(acc[q]);
}

// ---------------- masked softmax, fp16 in-place in g_sh ----------------
__global__ __launch_bounds__(256) void softmax_cross() {
    int row = blockIdx.x * 8 + (threadIdx.x >> 5);
    int lane = threadIdx.x & 31;
    int bn = row >> 7;
    bool v = g_valid[bn] != 0;
    __half* s = g_sh + (size_t)row * SPAD_;
    float vals[8];
    float m = -FLT_MAX;
#pragma unroll
    for (int i = 0; i < 8; i++) {
        int k = lane + i * 32;
        bool active = (k < P2_) && (v || k == 0);
        float x = active ? __half2float(s[k]) : 0.0f;
        vals[i] = active ? x : -INFINITY;
        m = fmaxf(m, vals[i]);
    }
#pragma unroll
    for (int o = 16; o; o >>= 1) m = fmaxf(m, __shfl_xor_sync(0xffffffffu, m, o));
    float sum = 0.0f;
#pragma unroll
    for (int i = 0; i < 8; i++) {
        int k = lane + i * 32;
        bool active = (k < P2_) && (v || k == 0);
        float e = active ? expf(vals[i] - m) : 0.0f;
        vals[i] = e;
        sum += e;
    }
#pragma unroll
    for (int o = 16; o; o >>= 1) sum += __shfl_xor_sync(0xffffffffu, sum, o);
    float inv = 1.0f / sum;
#pragma unroll
    for (int i = 0; i < 8; i++) {
        int k = lane + i * 32;
        if (k < P2_)        s[k] = __float2half_rn(vals[i] * inv);
        else if (k < SPAD_) s[k] = __float2half_rn(0.0f);
    }
}

// ---------------- cross-attn output: ctx = T @ Wv_h^T + bv (fp16 T in) ----------------
__global__ __launch_bounds__(512) void cross_o(const float* __restrict__ Wv,
                                               const float* __restrict__ bv) {
    int h = blockIdx.x, bn = blockIdx.y;
    __shared__ float ws[DH_][HID_ + 1];
    int t = threadIdx.x;
    for (int i = t; i < DH_ * HID_; i += 512) {
        int d = i >> 8, c = i & 255;
        ws[d][c] = Wv[(size_t)(h * DH_ + d) * HID_ + c];
    }
    __syncthreads();
    int q = t >> 5, d = t & 31;
    const __half* trow = g_uh + ((size_t)bn * 128 + h * NQ_ + q) * HID_;
    float acc = 0.0f;
#pragma unroll 4
    for (int c = 0; c < HID_; c += 2) {
        __half2 hv = *reinterpret_cast<const __half2*>(trow + c);
        float2 f = __half22float2(hv);
        acc += f.x * ws[d][c] + f.y * ws[d][c + 1];
    }
    g_ctx_h[((size_t)bn * NQ_ + q) * HID_ + h * DH_ + d] = __float2half_rn(acc + bv[h * DH_ + d]);
}

// ---------------- layernorm: writes fp32 + fp16 ----------------
__global__ __launch_bounds__(256) void layernorm_k(const float* __restrict__ X,
                                                   const float* __restrict__ w,
                                                   const float* __restrict__ b,
                                                   float* __restrict__ Y,
                                                   __half* __restrict__ Y16) {
    int row = blockIdx.x * 8 + (threadIdx.x >> 5);
    int lane = threadIdx.x & 31;
    const float* x = X + (size_t)row * HID_;
    float v[8];
    float s = 0.0f;
#pragma unroll
    for (int i = 0; i < 8; i++) { v[i] = x[lane + i * 32]; s += v[i]; }
#pragma unroll
    for (int o = 16; o; o >>= 1) s += __shfl_xor_sync(0xffffffffu, s, o);
    float mu = s * (1.0f / 256.0f);
    float var = 0.0f;
#pragma unroll
    for (int i = 0; i < 8; i++) { float d = v[i] - mu; var += d * d; }
#pragma unroll
    for (int o = 16; o; o >>= 1) var += __shfl_xor_sync(0xffffffffu, var, o);
    var *= (1.0f / 256.0f);
    float r = rsqrtf(var + LN_EPS_);
    float* y = Y + (size_t)row * HID_;
    __half* y16 = Y16 + (size_t)row * HID_;
#pragma unroll
    for (int i = 0; i < 8; i++) {
        int c = lane + i * 32;
        float out = (v[i] - mu) * r * w[c] + b[c];
        y[c] = out;
        y16[c] = __float2half_rn(out);
    }
}

// ---------------- final head ----------------
__global__ __launch_bounds__(256) void final_out(const float* __restrict__ W,
                                                 const float* __restrict__ bias,
                                                 float* __restrict__ out) {
    int row = blockIdx.x * 8 + (threadIdx.x >> 5);
    int lane = threadIdx.x & 31;
    const float* x = g_tgt + (size_t)row * HID_;
    float acc[4] = {};
#pragma unroll
    for (int i = 0; i < 8; i++) {
        int c = lane + i * 32;
        float xv = x[c];
#pragma unroll
        for (int j = 0; j < 4; j++) acc[j] += xv * W[j * HID_ + c];
    }
#pragma unroll
    for (int j = 0; j < 4; j++)
#pragma unroll
        for (int o = 16; o; o >>= 1) acc[j] += __shfl_xor_sync(0xffffffffu, acc[j], o);
    if (lane < 4) out[(size_t)row * 4 + lane] = acc[lane] + bias[lane];
}

// ---------------- host ----------------
extern "C" void kernel_launch(void* const* d_in, const int* in_sizes, int n_in,
                              void* d_out, int out_size) {
    (void)in_sizes; (void)n_in; (void)out_size;
    const float* img         = (const float*)d_in[0];
    const float* kp          = (const float*)d_in[1];
    const unsigned char* msk = (const unsigned char*)d_in[2];
    const float* proj_w      = (const float*)d_in[3];
    const float* proj_b      = (const float*)d_in[4];
    const float* query_embed = (const float*)d_in[5];
    const float* self_qkv_w  = (const float*)d_in[6];
    const float* self_qkv_b  = (const float*)d_in[7];
    const float* self_out_w  = (const float*)d_in[8];
    const float* self_out_b  = (const float*)d_in[9];
    const float* cross_qkv_w = (const float*)d_in[10];
    const float* cross_qkv_b = (const float*)d_in[11];
    const float* cross_out_w = (const float*)d_in[12];
    const float* cross_out_b = (const float*)d_in[13];
    const float* ffn1_w      = (const float*)d_in[14];
    const float* ffn1_b      = (const float*)d_in[15];
    const float* ffn2_w      = (const float*)d_in[16];
    const float* ffn2_b      = (const float*)d_in[17];
    const float* ln1_w       = (const float*)d_in[18];
    const float* ln1_b       = (const float*)d_in[19];
    const float* ln2_w       = (const float*)d_in[20];
    const float* ln2_b       = (const float*)d_in[21];
    const float* ln3_w       = (const float*)d_in[22];
    const float* ln3_b       = (const float*)d_in[23];
    const float* out_w       = (const float*)d_in[24];
    const float* out_b       = (const float*)d_in[25];
    float* out = (float*)d_out;

    float *tgt, *y;
    unsigned char* valid;
    __half *feat_h, *mem_h, *tgt_h, *ctx_h, *qkv_h, *qc_h, *uh, *sh, *ffn_h;
    __half *projw_h, *sqkv_h, *sout_h, *cqkv_h, *cout_h, *f1_h, *f2_h;
    cudaGetSymbolAddress((void**)&tgt,   g_tgt);
    cudaGetSymbolAddress((void**)&y,     g_y);
    cudaGetSymbolAddress((void**)&valid, g_valid);
    cudaGetSymbolAddress((void**)&feat_h, g_feat_h);
    cudaGetSymbolAddress((void**)&mem_h,  g_mem_h);
    cudaGetSymbolAddress((void**)&tgt_h,  g_tgt_h);
    cudaGetSymbolAddress((void**)&ctx_h,  g_ctx_h);
    cudaGetSymbolAddress((void**)&qkv_h,  g_qkv_h);
    cudaGetSymbolAddress((void**)&qc_h,   g_qc_h);
    cudaGetSymbolAddress((void**)&uh,     g_uh);
    cudaGetSymbolAddress((void**)&sh,     g_sh);
    cudaGetSymbolAddress((void**)&ffn_h,  g_ffn_h);
    cudaGetSymbolAddress((void**)&projw_h, g_projw_h);
    cudaGetSymbolAddress((void**)&sqkv_h,  g_sqkv_h);
    cudaGetSymbolAddress((void**)&sout_h,  g_sout_h);
    cudaGetSymbolAddress((void**)&cqkv_h,  g_cqkv_h);
    cudaGetSymbolAddress((void**)&cout_h,  g_cout_h);
    cudaGetSymbolAddress((void**)&f1_h,    g_f1_h);
    cudaGetSymbolAddress((void**)&f2_h,    g_f2_h);

    cudaFuncSetAttribute((const void*)gemm_h<true,  true,  false, false, true>,
                         cudaFuncAttributeMaxDynamicSharedMemorySize, GEMM_SMEM_);
    cudaFuncSetAttribute((const void*)gemm_h<true,  true,  true,  false, false>,
                         cudaFuncAttributeMaxDynamicSharedMemorySize, GEMM_SMEM_);
    cudaFuncSetAttribute((const void*)gemm_h<true,  false, false, false, true>,
                         cudaFuncAttributeMaxDynamicSharedMemorySize, GEMM_SMEM_);
    cudaFuncSetAttribute((const void*)gemm_h<false, false, false, false, true>,
                         cudaFuncAttributeMaxDynamicSharedMemorySize, GEMM_SMEM_);
    cudaFuncSetAttribute((const void*)gemm_h<true,  true,  false, true,  true>,
                         cudaFuncAttributeMaxDynamicSharedMemorySize, GEMM_SMEM_);

    const float scale = 0.17677669529663687f;

    decode_mask<<<1, 512>>>(msk, valid);
    { dim3 g(WF_, HF_, B_); transpose_img<<<g, C_>>>(img); }
    { dim3 g(P2_, N_KP, B_); roi_gather<<<g, C_>>>(kp); }

    f2h_all<<<(WT_ + 255) / 256, 256>>>(proj_w, self_qkv_w, self_out_w,
                                        cross_qkv_w, cross_out_w, ffn1_w, ffn2_w);

    // mem_h = fp16(feat @ proj_w^T + proj_b)
    gemm_h<true, true, false, false, true><<<dim3(2, 900, 1), 256, GEMM_SMEM_>>>(
        feat_h, projw_h, proj_b, nullptr, mem_h, MMEM_, HID_, C_, C_, C_, HID_, 0, 0, 0, 1.0f);

    init_tgt<<<MROWS_, 256>>>(query_embed);

    for (int l = 0; l < DEPTH_; l++) {
        const __half* sW  = sqkv_h + (size_t)l * 3 * 65536;
        const float*  sB  = self_qkv_b  + (size_t)l * 3 * HID_;
        const __half* soW = sout_h + (size_t)l * 65536;
        const float*  soB = self_out_b  + (size_t)l * HID_;
        const __half* cWq = cqkv_h + (size_t)l * 3 * 65536;
        const float*  cB  = cross_qkv_b + (size_t)l * 3 * HID_;
        const float*  cWf = cross_qkv_w + (size_t)l * 3 * HID_ * HID_;
        const __half* coW = cout_h + (size_t)l * 65536;
        const float*  coB = cross_out_b + (size_t)l * HID_;
        const __half* f1W = f1_h + (size_t)l * 262144;
        const float*  f1B = ffn1_b + (size_t)l * FFN_;
        const __half* f2W = f2_h + (size_t)l * 262144;
        const float*  f2B = ffn2_b + (size_t)l * HID_;

        // --- self attention ---
        gemm_h<true, true, false, false, true><<<dim3(6, 64, 1), 256, GEMM_SMEM_>>>(
            tgt_h, sW, sB, nullptr, qkv_h, MROWS_, 3 * HID_, HID_, HID_, HID_, 3 * HID_, 0, 0, 0, 1.0f);
        self_attn<<<BN_, 256>>>();
        gemm_h<true, true, true, false, false><<<dim3(2, 64, 1), 256, GEMM_SMEM_>>>(
            ctx_h, soW, soB, tgt, y, MROWS_, HID_, HID_, HID_, HID_, HID_, 0, 0, 0, 1.0f);
        layernorm_k<<<MROWS_ / 8, 256>>>(y, ln1_w + l * HID_, ln1_b + l * HID_, tgt, tgt_h);

        // --- cross attention (factored K/V) ---
        gemm_h<true, true, false, false, true><<<dim3(2, 64, 1), 256, GEMM_SMEM_>>>(
            tgt_h, cWq, cB, nullptr, qc_h, MROWS_, HID_, HID_, HID_, HID_, HID_, 0, 0, 0, 1.0f);
        { dim3 g(HEADS_, BN_); cross_u<<<g, 256>>>(cWf + (size_t)HID_ * HID_); }
        // S = fp16(scale * U @ mem^T), batched over bn
        gemm_h<true, false, false, false, true><<<dim3(2, 1, BN_), 256, GEMM_SMEM_>>>(
            uh, mem_h, nullptr, nullptr, sh, 128, P2_, HID_, HID_, HID_, SPAD_,
            (long long)128 * HID_, (long long)P2_ * HID_, (long long)128 * SPAD_, scale);
        softmax_cross<<<(BN_ * 128) / 8, 256>>>();
        // T = fp16(A @ mem), batched NT — K=225; sh pad cols are zero
        gemm_h<false, false, false, false, true><<<dim3(2, 1, BN_), 256, GEMM_SMEM_>>>(
            sh, mem_h, nullptr, nullptr, uh, 128, HID_, P2_, SPAD_, HID_, HID_,
            (long long)128 * SPAD_, (long long)P2_ * HID_, (long long)128 * HID_, 1.0f);
        { dim3 g(HEADS_, BN_); cross_o<<<g, 512>>>(cWf + (size_t)2 * HID_ * HID_, cB + 2 * HID_); }
        gemm_h<true, true, true, false, false><<<dim3(2, 64, 1), 256, GEMM_SMEM_>>>(
            ctx_h, coW, coB, tgt, y, MROWS_, HID_, HID_, HID_, HID_, HID_, 0, 0, 0, 1.0f);
        layernorm_k<<<MROWS_ / 8, 256>>>(y, ln2_w + l * HID_, ln2_b + l * HID_, tgt, tgt_h);

        // --- FFN ---
        gemm_h<true, true, false, true, true><<<dim3(8, 64, 1), 256, GEMM_SMEM_>>>(
            tgt_h, f1W, f1B, nullptr, ffn_h, MROWS_, FFN_, HID_, HID_, HID_, FFN_, 0, 0, 0, 1.0f);
        gemm_h<true, true, true, false, false><<<dim3(2, 64, 1), 256, GEMM_SMEM_>>>(
            ffn_h, f2W, f2B, tgt, y, MROWS_, HID_, FFN_, FFN_, FFN_, HID_, 0, 0, 0, 1.0f);
        layernorm_k<<<MROWS_ / 8, 256>>>(y, ln3_w + l * HID_, ln3_b + l * HID_, tgt, tgt_h);
    }

    final_out<<<MROWS_ / 8, 256>>>(out_w, out_b, out);
}

// round 14
// speedup vs baseline: 1.0040x; 1.0040x over previous
#include <cuda_runtime.h>
#include <cuda_fp16.h>
#include <math.h>
#include <float.h>
#include <stdint.h>

#define B_      2
#define N_KP    256
#define C_      256
#define HF_     64
#define WF_     64
#define ROI_    15
#define P2_     225
#define HID_    256
#define HEADS_  8
#define DH_     32
#define DEPTH_  3
#define FFN_    1024
#define NQ_     16
#define BN_     512          // B_*N_KP
#define MROWS_  8192         // BN_*NQ_
#define MMEM_   115200       // BN_*P2_
#define SPAD_   240          // padded S row; cols 225..239 zeroed
#define LN_EPS_ 1e-5f

#define STG_HALVES_ 5120
#define GEMM_SMEM_  (3 * 2 * STG_HALVES_ * 2)    // 61440 B

// ---------------- scratch ----------------
__device__ float g_imgT[(size_t)B_ * HF_ * WF_ * C_];
__device__ float g_tgt [(size_t)MROWS_ * HID_];
__device__ float g_y   [(size_t)MROWS_ * HID_];
__device__ unsigned char g_valid[BN_];

// fp16 activations
__device__ __half g_feat_h[(size_t)MMEM_ * C_];
__device__ __half g_mem_h [(size_t)MMEM_ * C_];
__device__ __half g_tgt_h [(size_t)MROWS_ * HID_];
__device__ __half g_ctx_h [(size_t)MROWS_ * HID_];
__device__ __half g_qkv_h [(size_t)MROWS_ * 3 * HID_];
__device__ __half g_qc_h  [(size_t)MROWS_ * HID_];
__device__ __half g_uh    [(size_t)BN_ * 128 * HID_];  // U, then T
__device__ __half g_sh    [(size_t)BN_ * 128 * SPAD_];
__device__ __half g_ffn_h [(size_t)MROWS_ * FFN_];
// fp16 weights
__device__ __half g_projw_h[65536];
__device__ __half g_sqkv_h [3 * 3 * 65536];
__device__ __half g_sout_h [3 * 65536];
__device__ __half g_cqkv_h [3 * 3 * 65536];
__device__ __half g_cout_h [3 * 65536];
__device__ __half g_f1_h   [3 * 262144];
__device__ __half g_f2_h   [3 * 262144];

// ---------------- helpers ----------------
__device__ __forceinline__ void mma_f16(float* c, const uint32_t* a, const uint32_t* b) {
    asm volatile(
        "mma.sync.aligned.m16n8k16.row.col.f32.f16.f16.f32 "
        "{%0,%1,%2,%3}, {%4,%5,%6,%7}, {%8,%9}, {%0,%1,%2,%3};\n"
        : "+f"(c[0]), "+f"(c[1]), "+f"(c[2]), "+f"(c[3])
        : "r"(a[0]), "r"(a[1]), "r"(a[2]), "r"(a[3]), "r"(b[0]), "r"(b[1]));
}

__device__ __forceinline__ void ldsm4(uint32_t* r, uint32_t saddr) {
    asm volatile("ldmatrix.sync.aligned.m8n8.x4.shared.b16 {%0,%1,%2,%3}, [%4];\n"
                 : "=r"(r[0]), "=r"(r[1]), "=r"(r[2]), "=r"(r[3]) : "r"(saddr));
}
__device__ __forceinline__ void ldsm4t(uint32_t* r, uint32_t saddr) {
    asm volatile("ldmatrix.sync.aligned.m8n8.x4.trans.shared.b16 {%0,%1,%2,%3}, [%4];\n"
                 : "=r"(r[0]), "=r"(r[1]), "=r"(r[2]), "=r"(r[3]) : "r"(saddr));
}

__device__ __forceinline__ void cpa16(void* smem_ptr, const void* gptr, bool pred) {
    uint32_t sa = (uint32_t)__cvta_generic_to_shared(smem_ptr);
    int sz = pred ? 16 : 0;
    asm volatile("cp.async.cg.shared.global [%0], [%1], 16, %2;\n"
                 :: "r"(sa), "l"(gptr), "r"(sz));
}
#define CPA_COMMIT() asm volatile("cp.async.commit_group;\n")
#define CPA_WAIT(n)  asm volatile("cp.async.wait_group %0;\n" :: "n"(n))

// ---------------- fused weight convert ----------------
#define W0_ 65536
#define W1_ 589824
#define W2_ 196608
#define W3_ 589824
#define W4_ 196608
#define W5_ 786432
#define W6_ 786432
#define WT_ (W0_+W1_+W2_+W3_+W4_+W5_+W6_)

__global__ void f2h_all(const float* __restrict__ p0, const float* __restrict__ p1,
                        const float* __restrict__ p2, const float* __restrict__ p3,
                        const float* __restrict__ p4, const float* __restrict__ p5,
                        const float* __restrict__ p6) {
    long i = (long)blockIdx.x * 256 + threadIdx.x;
    if (i >= WT_) return;
    long o = i;
    if (o < W0_) { g_projw_h[o] = __float2half_rn(p0[o]); return; } o -= W0_;
    if (o < W1_) { g_sqkv_h[o]  = __float2half_rn(p1[o]); return; } o -= W1_;
    if (o < W2_) { g_sout_h[o]  = __float2half_rn(p2[o]); return; } o -= W2_;
    if (o < W3_) { g_cqkv_h[o]  = __float2half_rn(p3[o]); return; } o -= W3_;
    if (o < W4_) { g_cout_h[o]  = __float2half_rn(p4[o]); return; } o -= W4_;
    if (o < W5_) { g_f1_h[o]    = __float2half_rn(p5[o]); return; } o -= W5_;
    g_f2_h[o] = __float2half_rn(p6[o]);
}

__global__ void decode_mask(const unsigned char* __restrict__ m, unsigned char* __restrict__ out) {
    __shared__ int flag;
    if (threadIdx.x == 0) flag = 0;
    __syncthreads();
    int i = threadIdx.x;
    unsigned char v8 = m[i];
    if ((i & 3) != 0 && v8 != 0) atomicOr(&flag, 1);
    __syncthreads();
    if (flag) out[i] = (v8 != 0);
    else      out[i] = (((const int*)m)[i] != 0);
}

// ---------------- coalesced image transpose (B,C,HW) -> (B,HW,C) ----------------
// 32x32 smem tile per block; 256 threads 1-D. grid (128, 8, B_).
__global__ __launch_bounds__(256) void transpose_img(const float* __restrict__ img) {
    __shared__ float tile[32][33];
    int b = blockIdx.z;
    int s0 = blockIdx.x * 32;        // spatial (HW) base
    int c0 = blockIdx.y * 32;        // channel base
    int t = threadIdx.x;
    int tx = t & 31;
    int r0 = t >> 5;                 // 0..7
    const float* src = img + (size_t)b * C_ * 4096;
#pragma unroll
    for (int p = 0; p < 4; p++) {
        int i = r0 + p * 8;
        tile[i][tx] = src[(size_t)(c0 + i) * 4096 + s0 + tx];   // coalesced along s
    }
    __syncthreads();
    float* dst = g_imgT + (size_t)b * 4096 * C_;
#pragma unroll
    for (int p = 0; p < 4; p++) {
        int i = r0 + p * 8;
        dst[(size_t)(s0 + i) * C_ + c0 + tx] = tile[tx][i];     // coalesced along c
    }
}

// ---------------- ROI bilinear gather -> fp16 feat ----------------
__global__ __launch_bounds__(256) void roi_gather(const float* __restrict__ kp) {
    int p = blockIdx.x, n = blockIdx.y, b = blockIdx.z, c = threadIdx.x;
    int iy = p / ROI_, ix = p % ROI_;
    float rc0 = rintf(kp[((size_t)b * N_KP + n) * 2 + 0]);
    float rc1 = rintf(kp[((size_t)b * N_KP + n) * 2 + 1]);
    float gy = rc0 + (float)(iy - 7);
    float gx = rc1 + (float)(ix - 7);
    float gxn = __fdiv_rn(gx, 511.0f) * 2.0f - 1.0f;
    float gyn = __fdiv_rn(gy, 511.0f) * 2.0f - 1.0f;
    bool invalid = (gxn < -1.0f) || (gyn < -1.0f) || (gxn > 1.0f) || (gyn > 1.0f);
    __half* dst = g_feat_h + ((size_t)((b * N_KP + n) * P2_ + p)) * C_;
    if (invalid) { dst[c] = __float2half_rn(0.0f); return; }
    float x = ((gxn + 1.0f) * (float)WF_ - 1.0f) * 0.5f;
    float y = ((gyn + 1.0f) * (float)HF_ - 1.0f) * 0.5f;
    float x0f = floorf(x), y0f = floorf(y);
    float wx = x - x0f, wy = y - y0f;
    int x0 = (int)x0f, y0 = (int)y0f;
    int x1 = x0 + 1, y1 = y0 + 1;
    float w00 = (1.0f - wy) * (1.0f - wx);
    float w01 = (1.0f - wy) * wx;
    float w10 = wy * (1.0f - wx);
    float w11 = wy * wx;
    float acc = 0.0f;
    if (y0 >= 0 && y0 < HF_) {
        const float* rowp = g_imgT + ((size_t)(b * HF_ + y0) * WF_) * C_;
        if (x0 >= 0 && x0 < WF_) acc += w00 * rowp[(size_t)x0 * C_ + c];
        if (x1 >= 0 && x1 < WF_) acc += w01 * rowp[(size_t)x1 * C_ + c];
    }
    if (y1 >= 0 && y1 < HF_) {
        const float* rowp = g_imgT + ((size_t)(b * HF_ + y1) * WF_) * C_;
        if (x0 >= 0 && x0 < WF_) acc += w10 * rowp[(size_t)x0 * C_ + c];
        if (x1 >= 0 && x1 < WF_) acc += w11 * rowp[(size_t)x1 * C_ + c];
    }
    dst[c] = __float2half_rn(acc);
}

// ================= fp16 GEMM (ldmatrix + 3-stage cp.async, K-tile 32) =================
template<bool TB, bool HAS_BIAS, bool HAS_RES, bool RELU, bool OUT16>
__global__ __launch_bounds__(256, 2) void gemm_h(
    const __half* __restrict__ A, const __half* __restrict__ B,
    const float* __restrict__ bias, const float* __restrict__ Res,
    void* __restrict__ Cv,
    int M, int N, int K, int lda, int ldb, int ldc,
    long long sA, long long sB, long long sC, float alpha)
{
    extern __shared__ __half hsm[];
    __half* Asm = hsm;
    __half* Bsm = hsm + 3 * STG_HALVES_;

    long long z = blockIdx.z;
    A += z * sA; B += z * sB;
    float* Cf = (float*)Cv + (OUT16 ? 0 : z * sC);
    __half* Ch = (__half*)Cv + (OUT16 ? z * sC : 0);
    if (HAS_RES) Res += z * sC;

    int m0 = blockIdx.y * 128, n0 = blockIdx.x * 128;
    int t = threadIdx.x;
    int wid = t >> 5, lane = t & 31;
    int warp_m = wid >> 2;
    int warp_n = wid & 3;

    int l7 = lane & 7;
    int gidx = lane >> 3;

    uint32_t As_u = (uint32_t)__cvta_generic_to_shared(Asm);
    uint32_t Bs_u = (uint32_t)__cvta_generic_to_shared(Bsm);
    uint32_t a_lane  = (uint32_t)(((l7 + (gidx & 1) * 8) * 40 + (gidx >> 1) * 8) * 2);
    uint32_t bt_lane = a_lane;
    uint32_t bn_lane = (uint32_t)(((l7 + (gidx >> 1) * 8) * 136 + (gidx & 1) * 8) * 2);

    float acc[4][4][4];
#pragma unroll
    for (int i = 0; i < 4; i++)
#pragma unroll
        for (int j = 0; j < 4; j++)
#pragma unroll
            for (int r = 0; r < 4; r++) acc[i][j][r] = 0.0f;

    int KT = (K + 31) >> 5;

    auto load_tile = [&](int st, int k0) {
#pragma unroll
        for (int i = 0; i < 2; i++) {
            int lin = t + i * 256;
            int row = lin >> 2;
            int kc  = (lin & 3) * 8;
            int gm = m0 + row, gk = k0 + kc;
            cpa16(&Asm[st * STG_HALVES_ + row * 40 + kc],
                  A + (size_t)gm * lda + gk, gm < M && gk < K);
        }
        if (TB) {
#pragma unroll
            for (int i = 0; i < 2; i++) {
                int lin = t + i * 256;
                int row = lin >> 2;
                int kc  = (lin & 3) * 8;
                int gn = n0 + row, gk = k0 + kc;
                cpa16(&Bsm[st * STG_HALVES_ + row * 40 + kc],
                      B + (size_t)gn * ldb + gk, gn < N && gk < K);
            }
        } else {
#pragma unroll
            for (int i = 0; i < 2; i++) {
                int lin = t + i * 256;
                int kk = lin >> 4;
                int nc = (lin & 15) * 8;
                int gk = k0 + kk;
                cpa16(&Bsm[st * STG_HALVES_ + kk * 136 + nc],
                      B + (size_t)gk * ldb + n0 + nc, gk < K);
            }
        }
    };

    load_tile(0, 0); CPA_COMMIT();
    if (1 < KT) { load_tile(1, 32); CPA_COMMIT(); }

    for (int kt = 0; kt < KT; kt++) {
        if (kt + 1 < KT) { CPA_WAIT(1); } else { CPA_WAIT(0); }
        __syncthreads();
        if (kt + 2 < KT) { load_tile((kt + 2) % 3, (kt + 2) * 32); CPA_COMMIT(); }

        int st = kt % 3;
        uint32_t stoff = (uint32_t)(st * STG_HALVES_ * 2);
#pragma unroll
        for (int ks = 0; ks < 32; ks += 16) {
            uint32_t af[4][4];
#pragma unroll
            for (int mt = 0; mt < 4; mt++)
                ldsm4(af[mt], As_u + stoff +
                      (uint32_t)(((warp_m * 64 + mt * 16) * 40 + ks) * 2) + a_lane);
            uint32_t bf[4][2];
#pragma unroll
            for (int np = 0; np < 2; np++) {
                uint32_t tmp[4];
                if (TB) {
                    ldsm4(tmp, Bs_u + stoff +
                          (uint32_t)(((warp_n * 32 + np * 16) * 40 + ks) * 2) + bt_lane);
                } else {
                    ldsm4t(tmp, Bs_u + stoff +
                           (uint32_t)((ks * 136 + warp_n * 32 + np * 16) * 2) + bn_lane);
                }
                bf[2 * np][0]     = tmp[0]; bf[2 * np][1]     = tmp[2];
                bf[2 * np + 1][0] = tmp[1]; bf[2 * np + 1][1] = tmp[3];
            }
#pragma unroll
            for (int mt = 0; mt < 4; mt++)
#pragma unroll
                for (int nt = 0; nt < 4; nt++)
                    mma_f16(acc[mt][nt], af[mt], bf[nt]);
        }
    }

    // ---- epilogue ----
    int gq = lane >> 2, tq2 = lane & 3;
#pragma unroll
    for (int mt = 0; mt < 4; mt++) {
        int row0 = m0 + warp_m * 64 + mt * 16 + gq;
#pragma unroll
        for (int nt = 0; nt < 4; nt++) {
            int col = n0 + warp_n * 32 + nt * 8 + tq2 * 2;
#pragma unroll
            for (int half = 0; half < 2; half++) {
                int row = row0 + half * 8;
                if (row >= M) continue;
#pragma unroll
                for (int e = 0; e < 2; e++) {
                    int cc = col + e;
                    if (cc >= N) continue;
                    float v = acc[mt][nt][half * 2 + e] * alpha;
                    if (HAS_BIAS) v += bias[cc];
                    if (HAS_RES)  v += Res[(size_t)row * ldc + cc];
                    if (RELU)     v = fmaxf(v, 0.0f);
                    if (OUT16) Ch[(size_t)row * ldc + cc] = __float2half_rn(v);
                    else       Cf[(size_t)row * ldc + cc] = v;
                }
            }
        }
    }
}

// ---------------- tgt init ----------------
__global__ void init_tgt(const float* __restrict__ qe) {
    size_t i = (size_t)blockIdx.x * 256 + threadIdx.x;
    int c = (int)(i & 255);
    int q = (int)((i >> 8) & 15);
    float v = qe[q * HID_ + c];
    g_tgt[i] = v;
    g_tgt_h[i] = __float2half_rn(v);
}

// ---------------- self attention ----------------
__global__ __launch_bounds__(256) void self_attn() {
    int bn = blockIdx.x;
    __shared__ float sq[NQ_][260];
    __shared__ float sk[NQ_][260];
    __shared__ float sa[HEADS_][NQ_][NQ_ + 1];
    int t = threadIdx.x;
    const __half* base = g_qkv_h + (size_t)bn * NQ_ * 768;
    for (int i = t; i < NQ_ * HID_; i += 256) {
        int q = i >> 8, c = i & 255;
        sq[q][c] = __half2float(base[q * 768 + c]);
        sk[q][c] = __half2float(base[q * 768 + 256 + c]);
    }
    __syncthreads();
    const float scale = 0.17677669529663687f;
    for (int i = t; i < HEADS_ * NQ_ * NQ_; i += 256) {
        int h = i >> 8, q = (i >> 4) & 15, kk = i & 15;
        float acc = 0.0f;
#pragma unroll
        for (int d = 0; d < DH_; d++) acc += sq[q][h * DH_ + d] * sk[kk][h * DH_ + d];
        sa[h][q][kk] = acc * scale;
    }
    __syncthreads();
    if (t < HEADS_ * NQ_) {
        int h = t >> 4, q = t & 15;
        float m = -FLT_MAX;
#pragma unroll
        for (int kk = 0; kk < NQ_; kk++) m = fmaxf(m, sa[h][q][kk]);
        float s = 0.0f;
#pragma unroll
        for (int kk = 0; kk < NQ_; kk++) { float e = expf(sa[h][q][kk] - m); sa[h][q][kk] = e; s += e; }
        float inv = 1.0f / s;
#pragma unroll
        for (int kk = 0; kk < NQ_; kk++) sa[h][q][kk] *= inv;
    }
    __syncthreads();
    __half* out = g_ctx_h + (size_t)bn * NQ_ * HID_;
    for (int i = t; i < NQ_ * HID_; i += 256) {
        int q = i >> 8, c = i & 255;
        int h = c >> 5;
        float acc = 0.0f;
#pragma unroll
        for (int kk = 0; kk < NQ_; kk++)
            acc += sa[h][q][kk] * __half2float(base[kk * 768 + 512 + c]);
        out[q * HID_ + c] = __float2half_rn(acc);
    }
}

// ---------------- cross-attn U = Q_h @ Wk_h ----------------
__global__ __launch_bounds__(256) void cross_u(const float* __restrict__ Wk) {
    int h = blockIdx.x, bn = blockIdx.y;
    int c = threadIdx.x;
    __shared__ float sq[NQ_][DH_];
    for (int i = threadIdx.x; i < NQ_ * DH_; i += 256) {
        int q = i >> 5, d = i & 31;
        sq[q][d] = __half2float(g_qc_h[((size_t)bn * NQ_ + q) * HID_ + h * DH_ + d]);
    }
    __syncthreads();
    float acc[NQ_] = {};
#pragma unroll 4
    for (int d = 0; d < DH_; d++) {
        float w = Wk[(size_t)(h * DH_ + d) * HID_ + c];
#pragma unroll
        for (int q = 0; q < NQ_; q++) acc[q] += sq[q][d] * w;
    }
    __half* dst = g_uh + ((size_t)bn * 128 + h * NQ_) * HID_ + c;
#pragma unroll
    for (int q = 0; q < NQ_; q++) dst[(size_t)q * HID_] = __float2half_rn(acc[q]);
}

// ---------------- masked softmax, fp16 in-place in g_sh ----------------
__global__ __launch_bounds__(256) void softmax_cross() {
    int row = blockIdx.x * 8 + (threadIdx.x >> 5);
    int lane = threadIdx.x & 31;
    int bn = row >> 7;
    bool v = g_valid[bn] != 0;
    __half* s = g_sh + (size_t)row * SPAD_;
    float vals[8];
    float m = -FLT_MAX;
#pragma unroll
    for (int i = 0; i < 8; i++) {
        int k = lane + i * 32;
        bool active = (k < P2_) && (v || k == 0);
        float x = active ? __half2float(s[k]) : 0.0f;
        vals[i] = active ? x : -INFINITY;
        m = fmaxf(m, vals[i]);
    }
#pragma unroll
    for (int o = 16; o; o >>= 1) m = fmaxf(m, __shfl_xor_sync(0xffffffffu, m, o));
    float sum = 0.0f;
#pragma unroll
    for (int i = 0; i < 8; i++) {
        int k = lane + i * 32;
        bool active = (k < P2_) && (v || k == 0);
        float e = active ? expf(vals[i] - m) : 0.0f;
        vals[i] = e;
        sum += e;
    }
#pragma unroll
    for (int o = 16; o; o >>= 1) sum += __shfl_xor_sync(0xffffffffu, sum, o);
    float inv = 1.0f / sum;
#pragma unroll
    for (int i = 0; i < 8; i++) {
        int k = lane + i * 32;
        if (k < P2_)        s[k] = __float2half_rn(vals[i] * inv);
        else if (k < SPAD_) s[k] = __float2half_rn(0.0f);
    }
}

// ---------------- cross-attn output: ctx = T @ Wv_h^T + bv ----------------
__global__ __launch_bounds__(512) void cross_o(const float* __restrict__ Wv,
                                               const float* __restrict__ bv) {
    int h = blockIdx.x, bn = blockIdx.y;
    __shared__ float ws[DH_][HID_ + 1];
    int t = threadIdx.x;
    for (int i = t; i < DH_ * HID_; i += 512) {
        int d = i >> 8, c = i & 255;
        ws[d][c] = Wv[(size_t)(h * DH_ + d) * HID_ + c];
    }
    __syncthreads();
    int q = t >> 5, d = t & 31;
    const __half* trow = g_uh + ((size_t)bn * 128 + h * NQ_ + q) * HID_;
    float acc = 0.0f;
#pragma unroll 4
    for (int c = 0; c < HID_; c += 2) {
        __half2 hv = *reinterpret_cast<const __half2*>(trow + c);
        float2 f = __half22float2(hv);
        acc += f.x * ws[d][c] + f.y * ws[d][c + 1];
    }
    g_ctx_h[((size_t)bn * NQ_ + q) * HID_ + h * DH_ + d] = __float2half_rn(acc + bv[h * DH_ + d]);
}

// ---------------- layernorm: writes fp32 + fp16 ----------------
__global__ __launch_bounds__(256) void layernorm_k(const float* __restrict__ X,
                                                   const float* __restrict__ w,
                                                   const float* __restrict__ b,
                                                   float* __restrict__ Y,
                                                   __half* __restrict__ Y16) {
    int row = blockIdx.x * 8 + (threadIdx.x >> 5);
    int lane = threadIdx.x & 31;
    const float* x = X + (size_t)row * HID_;
    float v[8];
    float s = 0.0f;
#pragma unroll
    for (int i = 0; i < 8; i++) { v[i] = x[lane + i * 32]; s += v[i]; }
#pragma unroll
    for (int o = 16; o; o >>= 1) s += __shfl_xor_sync(0xffffffffu, s, o);
    float mu = s * (1.0f / 256.0f);
    float var = 0.0f;
#pragma unroll
    for (int i = 0; i < 8; i++) { float d = v[i] - mu; var += d * d; }
#pragma unroll
    for (int o = 16; o; o >>= 1) var += __shfl_xor_sync(0xffffffffu, var, o);
    var *= (1.0f / 256.0f);
    float r = rsqrtf(var + LN_EPS_);
    float* y = Y + (size_t)row * HID_;
    __half* y16 = Y16 + (size_t)row * HID_;
#pragma unroll
    for (int i = 0; i < 8; i++) {
        int c = lane + i * 32;
        float out = (v[i] - mu) * r * w[c] + b[c];
        y[c] = out;
        y16[c] = __float2half_rn(out);
    }
}

// ---------------- final head ----------------
__global__ __launch_bounds__(256) void final_out(const float* __restrict__ W,
                                                 const float* __restrict__ bias,
                                                 float* __restrict__ out) {
    int row = blockIdx.x * 8 + (threadIdx.x >> 5);
    int lane = threadIdx.x & 31;
    const float* x = g_tgt + (size_t)row * HID_;
    float acc[4] = {};
#pragma unroll
    for (int i = 0; i < 8; i++) {
        int c = lane + i * 32;
        float xv = x[c];
#pragma unroll
        for (int j = 0; j < 4; j++) acc[j] += xv * W[j * HID_ + c];
    }
#pragma unroll
    for (int j = 0; j < 4; j++)
#pragma unroll
        for (int o = 16; o; o >>= 1) acc[j] += __shfl_xor_sync(0xffffffffu, acc[j], o);
    if (lane < 4) out[(size_t)row * 4 + lane] = acc[lane] + bias[lane];
}

// ---------------- host ----------------
extern "C" void kernel_launch(void* const* d_in, const int* in_sizes, int n_in,
                              void* d_out, int out_size) {
    (void)in_sizes; (void)n_in; (void)out_size;
    const float* img         = (const float*)d_in[0];
    const float* kp          = (const float*)d_in[1];
    const unsigned char* msk = (const unsigned char*)d_in[2];
    const float* proj_w      = (const float*)d_in[3];
    const float* proj_b      = (const float*)d_in[4];
    const float* query_embed = (const float*)d_in[5];
    const float* self_qkv_w  = (const float*)d_in[6];
    const float* self_qkv_b  = (const float*)d_in[7];
    const float* self_out_w  = (const float*)d_in[8];
    const float* self_out_b  = (const float*)d_in[9];
    const float* cross_qkv_w = (const float*)d_in[10];
    const float* cross_qkv_b = (const float*)d_in[11];
    const float* cross_out_w = (const float*)d_in[12];
    const float* cross_out_b = (const float*)d_in[13];
    const float* ffn1_w      = (const float*)d_in[14];
    const float* ffn1_b      = (const float*)d_in[15];
    const float* ffn2_w      = (const float*)d_in[16];
    const float* ffn2_b      = (const float*)d_in[17];
    const float* ln1_w       = (const float*)d_in[18];
    const float* ln1_b       = (const float*)d_in[19];
    const float* ln2_w       = (const float*)d_in[20];
    const float* ln2_b       = (const float*)d_in[21];
    const float* ln3_w       = (const float*)d_in[22];
    const float* ln3_b       = (const float*)d_in[23];
    const float* out_w       = (const float*)d_in[24];
    const float* out_b       = (const float*)d_in[25];
    float* out = (float*)d_out;

    float *tgt, *y;
    unsigned char* valid;
    __half *feat_h, *mem_h, *tgt_h, *ctx_h, *qkv_h, *qc_h, *uh, *sh, *ffn_h;
    __half *projw_h, *sqkv_h, *sout_h, *cqkv_h, *cout_h, *f1_h, *f2_h;
    cudaGetSymbolAddress((void**)&tgt,   g_tgt);
    cudaGetSymbolAddress((void**)&y,     g_y);
    cudaGetSymbolAddress((void**)&valid, g_valid);
    cudaGetSymbolAddress((void**)&feat_h, g_feat_h);
    cudaGetSymbolAddress((void**)&mem_h,  g_mem_h);
    cudaGetSymbolAddress((void**)&tgt_h,  g_tgt_h);
    cudaGetSymbolAddress((void**)&ctx_h,  g_ctx_h);
    cudaGetSymbolAddress((void**)&qkv_h,  g_qkv_h);
    cudaGetSymbolAddress((void**)&qc_h,   g_qc_h);
    cudaGetSymbolAddress((void**)&uh,     g_uh);
    cudaGetSymbolAddress((void**)&sh,     g_sh);
    cudaGetSymbolAddress((void**)&ffn_h,  g_ffn_h);
    cudaGetSymbolAddress((void**)&projw_h, g_projw_h);
    cudaGetSymbolAddress((void**)&sqkv_h,  g_sqkv_h);
    cudaGetSymbolAddress((void**)&sout_h,  g_sout_h);
    cudaGetSymbolAddress((void**)&cqkv_h,  g_cqkv_h);
    cudaGetSymbolAddress((void**)&cout_h,  g_cout_h);
    cudaGetSymbolAddress((void**)&f1_h,    g_f1_h);
    cudaGetSymbolAddress((void**)&f2_h,    g_f2_h);

    cudaFuncSetAttribute((const void*)gemm_h<true,  true,  false, false, true>,
                         cudaFuncAttributeMaxDynamicSharedMemorySize, GEMM_SMEM_);
    cudaFuncSetAttribute((const void*)gemm_h<true,  true,  true,  false, false>,
                         cudaFuncAttributeMaxDynamicSharedMemorySize, GEMM_SMEM_);
    cudaFuncSetAttribute((const void*)gemm_h<true,  false, false, false, true>,
                         cudaFuncAttributeMaxDynamicSharedMemorySize, GEMM_SMEM_);
    cudaFuncSetAttribute((const void*)gemm_h<false, false, false, false, true>,
                         cudaFuncAttributeMaxDynamicSharedMemorySize, GEMM_SMEM_);
    cudaFuncSetAttribute((const void*)gemm_h<true,  true,  false, true,  true>,
                         cudaFuncAttributeMaxDynamicSharedMemorySize, GEMM_SMEM_);

    const float scale = 0.17677669529663687f;

    decode_mask<<<1, 512>>>(msk, valid);
    { dim3 g(128, 8, B_); transpose_img<<<g, 256>>>(img); }
    { dim3 g(P2_, N_KP, B_); roi_gather<<<g, C_>>>(kp); }

    f2h_all<<<(WT_ + 255) / 256, 256>>>(proj_w, self_qkv_w, self_out_w,
                                        cross_qkv_w, cross_out_w, ffn1_w, ffn2_w);

    gemm_h<true, true, false, false, true><<<dim3(2, 900, 1), 256, GEMM_SMEM_>>>(
        feat_h, projw_h, proj_b, nullptr, mem_h, MMEM_, HID_, C_, C_, C_, HID_, 0, 0, 0, 1.0f);

    init_tgt<<<MROWS_, 256>>>(query_embed);

    for (int l = 0; l < DEPTH_; l++) {
        const __half* sW  = sqkv_h + (size_t)l * 3 * 65536;
        const float*  sB  = self_qkv_b  + (size_t)l * 3 * HID_;
        const __half* soW = sout_h + (size_t)l * 65536;
        const float*  soB = self_out_b  + (size_t)l * HID_;
        const __half* cWq = cqkv_h + (size_t)l * 3 * 65536;
        const float*  cB  = cross_qkv_b + (size_t)l * 3 * HID_;
        const float*  cWf = cross_qkv_w + (size_t)l * 3 * HID_ * HID_;
        const __half* coW = cout_h + (size_t)l * 65536;
        const float*  coB = cross_out_b + (size_t)l * HID_;
        const __half* f1W = f1_h + (size_t)l * 262144;
        const float*  f1B = ffn1_b + (size_t)l * FFN_;
        const __half* f2W = f2_h + (size_t)l * 262144;
        const float*  f2B = ffn2_b + (size_t)l * HID_;

        gemm_h<true, true, false, false, true><<<dim3(6, 64, 1), 256, GEMM_SMEM_>>>(
            tgt_h, sW, sB, nullptr, qkv_h, MROWS_, 3 * HID_, HID_, HID_, HID_, 3 * HID_, 0, 0, 0, 1.0f);
        self_attn<<<BN_, 256>>>();
        gemm_h<true, true, true, false, false><<<dim3(2, 64, 1), 256, GEMM_SMEM_>>>(
            ctx_h, soW, soB, tgt, y, MROWS_, HID_, HID_, HID_, HID_, HID_, 0, 0, 0, 1.0f);
        layernorm_k<<<MROWS_ / 8, 256>>>(y, ln1_w + l * HID_, ln1_b + l * HID_, tgt, tgt_h);

        gemm_h<true, true, false, false, true><<<dim3(2, 64, 1), 256, GEMM_SMEM_>>>(
            tgt_h, cWq, cB, nullptr, qc_h, MROWS_, HID_, HID_, HID_, HID_, HID_, 0, 0, 0, 1.0f);
        { dim3 g(HEADS_, BN_); cross_u<<<g, 256>>>(cWf + (size_t)HID_ * HID_); }
        gemm_h<true, false, false, false, true><<<dim3(2, 1, BN_), 256, GEMM_SMEM_>>>(
            uh, mem_h, nullptr, nullptr, sh, 128, P2_, HID_, HID_, HID_, SPAD_,
            (long long)128 * HID_, (long long)P2_ * HID_, (long long)128 * SPAD_, scale);
        softmax_cross<<<(BN_ * 128) / 8, 256>>>();
        gemm_h<false, false, false, false, true><<<dim3(2, 1, BN_), 256, GEMM_SMEM_>>>(
            sh, mem_h, nullptr, nullptr, uh, 128, HID_, P2_, SPAD_, HID_, HID_,
            (long long)128 * SPAD_, (long long)P2_ * HID_, (long long)128 * HID_, 1.0f);
        { dim3 g(HEADS_, BN_); cross_o<<<g, 512>>>(cWf + (size_t)2 * HID_ * HID_, cB + 2 * HID_); }
        gemm_h<true, true, true, false, false><<<dim3(2, 64, 1), 256, GEMM_SMEM_>>>(
            ctx_h, coW, coB, tgt, y, MROWS_, HID_, HID_, HID_, HID_, HID_, 0, 0, 0, 1.0f);
        layernorm_k<<<MROWS_ / 8, 256>>>(y, ln2_w + l * HID_, ln2_b + l * HID_, tgt, tgt_h);

        gemm_h<true, true, false, true, true><<<dim3(8, 64, 1), 256, GEMM_SMEM_>>>(
            tgt_h, f1W, f1B, nullptr, ffn_h, MROWS_, FFN_, HID_, HID_, HID_, FFN_, 0, 0, 0, 1.0f);
        gemm_h<true, true, true, false, false><<<dim3(2, 64, 1), 256, GEMM_SMEM_>>>(
            ffn_h, f2W, f2B, tgt, y, MROWS_, HID_, FFN_, FFN_, FFN_, HID_, 0, 0, 0, 1.0f);
        layernorm_k<<<MROWS_ / 8, 256>>>(y, ln3_w + l * HID_, ln3_b + l * HID_, tgt, tgt_h);
    }

    final_out<<<MROWS_ / 8, 256>>>(out_w, out_b, out);
}

// round 15
// speedup vs baseline: 1.0237x; 1.0197x over previous
#include <cuda_runtime.h>
#include <cuda_fp16.h>
#include <math.h>
#include <float.h>
#include <stdint.h>

#define B_      2
#define N_KP    256
#define C_      256
#define HF_     64
#define WF_     64
#define ROI_    15
#define P2_     225
#define HID_    256
#define HEADS_  8
#define DH_     32
#define DEPTH_  3
#define FFN_    1024
#define NQ_     16
#define BN_     512          // B_*N_KP
#define MROWS_  8192         // BN_*NQ_
#define MMEM_   115200       // BN_*P2_
#define SPAD_   240          // padded S row; cols 225..239 zeroed
#define LN_EPS_ 1e-5f

#define STG_HALVES_ 5120
#define GEMM_SMEM_  (3 * 2 * STG_HALVES_ * 2)    // 61440 B
// gemm_ln: A 64x40 (2560) + B 256x40 (10240) halves per stage, 3 stages, + LN floats
#define LNA_H_   2560
#define LNB_H_   10240
#define LN_SMEM_ (3 * (LNA_H_ + LNB_H_) * 2 + 4608)   // 81408 B

// ---------------- scratch ----------------
__device__ float g_imgT[(size_t)B_ * HF_ * WF_ * C_];
__device__ float g_tgt [(size_t)MROWS_ * HID_];
__device__ unsigned char g_valid[BN_];

// fp16 activations
__device__ __half g_feat_h[(size_t)MMEM_ * C_];
__device__ __half g_mem_h [(size_t)MMEM_ * C_];
__device__ __half g_tgt_h [(size_t)MROWS_ * HID_];
__device__ __half g_ctx_h [(size_t)MROWS_ * HID_];
__device__ __half g_qkv_h [(size_t)MROWS_ * 3 * HID_];
__device__ __half g_qc_h  [(size_t)MROWS_ * HID_];
__device__ __half g_uh    [(size_t)BN_ * 128 * HID_];  // U, then T
__device__ __half g_sh    [(size_t)BN_ * 128 * SPAD_];
__device__ __half g_ffn_h [(size_t)MROWS_ * FFN_];
// fp16 weights
__device__ __half g_projw_h[65536];
__device__ __half g_sqkv_h [3 * 3 * 65536];
__device__ __half g_sout_h [3 * 65536];
__device__ __half g_cqkv_h [3 * 3 * 65536];
__device__ __half g_cout_h [3 * 65536];
__device__ __half g_f1_h   [3 * 262144];
__device__ __half g_f2_h   [3 * 262144];

// ---------------- helpers ----------------
__device__ __forceinline__ void mma_f16(float* c, const uint32_t* a, const uint32_t* b) {
    asm volatile(
        "mma.sync.aligned.m16n8k16.row.col.f32.f16.f16.f32 "
        "{%0,%1,%2,%3}, {%4,%5,%6,%7}, {%8,%9}, {%0,%1,%2,%3};\n"
        : "+f"(c[0]), "+f"(c[1]), "+f"(c[2]), "+f"(c[3])
        : "r"(a[0]), "r"(a[1]), "r"(a[2]), "r"(a[3]), "r"(b[0]), "r"(b[1]));
}

__device__ __forceinline__ void ldsm4(uint32_t* r, uint32_t saddr) {
    asm volatile("ldmatrix.sync.aligned.m8n8.x4.shared.b16 {%0,%1,%2,%3}, [%4];\n"
                 : "=r"(r[0]), "=r"(r[1]), "=r"(r[2]), "=r"(r[3]) : "r"(saddr));
}
__device__ __forceinline__ void ldsm4t(uint32_t* r, uint32_t saddr) {
    asm volatile("ldmatrix.sync.aligned.m8n8.x4.trans.shared.b16 {%0,%1,%2,%3}, [%4];\n"
                 : "=r"(r[0]), "=r"(r[1]), "=r"(r[2]), "=r"(r[3]) : "r"(saddr));
}

__device__ __forceinline__ void cpa16(void* smem_ptr, const void* gptr, bool pred) {
    uint32_t sa = (uint32_t)__cvta_generic_to_shared(smem_ptr);
    int sz = pred ? 16 : 0;
    asm volatile("cp.async.cg.shared.global [%0], [%1], 16, %2;\n"
                 :: "r"(sa), "l"(gptr), "r"(sz));
}
#define CPA_COMMIT() asm volatile("cp.async.commit_group;\n")
#define CPA_WAIT(n)  asm volatile("cp.async.wait_group %0;\n" :: "n"(n))

// ---------------- fused weight convert ----------------
#define W0_ 65536
#define W1_ 589824
#define W2_ 196608
#define W3_ 589824
#define W4_ 196608
#define W5_ 786432
#define W6_ 786432
#define WT_ (W0_+W1_+W2_+W3_+W4_+W5_+W6_)

__global__ void f2h_all(const float* __restrict__ p0, const float* __restrict__ p1,
                        const float* __restrict__ p2, const float* __restrict__ p3,
                        const float* __restrict__ p4, const float* __restrict__ p5,
                        const float* __restrict__ p6) {
    long i = (long)blockIdx.x * 256 + threadIdx.x;
    if (i >= WT_) return;
    long o = i;
    if (o < W0_) { g_projw_h[o] = __float2half_rn(p0[o]); return; } o -= W0_;
    if (o < W1_) { g_sqkv_h[o]  = __float2half_rn(p1[o]); return; } o -= W1_;
    if (o < W2_) { g_sout_h[o]  = __float2half_rn(p2[o]); return; } o -= W2_;
    if (o < W3_) { g_cqkv_h[o]  = __float2half_rn(p3[o]); return; } o -= W3_;
    if (o < W4_) { g_cout_h[o]  = __float2half_rn(p4[o]); return; } o -= W4_;
    if (o < W5_) { g_f1_h[o]    = __float2half_rn(p5[o]); return; } o -= W5_;
    g_f2_h[o] = __float2half_rn(p6[o]);
}

__global__ void decode_mask(const unsigned char* __restrict__ m, unsigned char* __restrict__ out) {
    __shared__ int flag;
    if (threadIdx.x == 0) flag = 0;
    __syncthreads();
    int i = threadIdx.x;
    unsigned char v8 = m[i];
    if ((i & 3) != 0 && v8 != 0) atomicOr(&flag, 1);
    __syncthreads();
    if (flag) out[i] = (v8 != 0);
    else      out[i] = (((const int*)m)[i] != 0);
}

// ---------------- coalesced image transpose ----------------
__global__ __launch_bounds__(256) void transpose_img(const float* __restrict__ img) {
    __shared__ float tile[32][33];
    int b = blockIdx.z;
    int s0 = blockIdx.x * 32;
    int c0 = blockIdx.y * 32;
    int t = threadIdx.x;
    int tx = t & 31;
    int r0 = t >> 5;
    const float* src = img + (size_t)b * C_ * 4096;
#pragma unroll
    for (int p = 0; p < 4; p++) {
        int i = r0 + p * 8;
        tile[i][tx] = src[(size_t)(c0 + i) * 4096 + s0 + tx];
    }
    __syncthreads();
    float* dst = g_imgT + (size_t)b * 4096 * C_;
#pragma unroll
    for (int p = 0; p < 4; p++) {
        int i = r0 + p * 8;
        dst[(size_t)(s0 + i) * C_ + c0 + tx] = tile[tx][i];
    }
}

// ---------------- ROI bilinear gather -> fp16 feat ----------------
__global__ __launch_bounds__(256) void roi_gather(const float* __restrict__ kp) {
    int p = blockIdx.x, n = blockIdx.y, b = blockIdx.z, c = threadIdx.x;
    int iy = p / ROI_, ix = p % ROI_;
    float rc0 = rintf(kp[((size_t)b * N_KP + n) * 2 + 0]);
    float rc1 = rintf(kp[((size_t)b * N_KP + n) * 2 + 1]);
    float gy = rc0 + (float)(iy - 7);
    float gx = rc1 + (float)(ix - 7);
    float gxn = __fdiv_rn(gx, 511.0f) * 2.0f - 1.0f;
    float gyn = __fdiv_rn(gy, 511.0f) * 2.0f - 1.0f;
    bool invalid = (gxn < -1.0f) || (gyn < -1.0f) || (gxn > 1.0f) || (gyn > 1.0f);
    __half* dst = g_feat_h + ((size_t)((b * N_KP + n) * P2_ + p)) * C_;
    if (invalid) { dst[c] = __float2half_rn(0.0f); return; }
    float x = ((gxn + 1.0f) * (float)WF_ - 1.0f) * 0.5f;
    float y = ((gyn + 1.0f) * (float)HF_ - 1.0f) * 0.5f;
    float x0f = floorf(x), y0f = floorf(y);
    float wx = x - x0f, wy = y - y0f;
    int x0 = (int)x0f, y0 = (int)y0f;
    int x1 = x0 + 1, y1 = y0 + 1;
    float w00 = (1.0f - wy) * (1.0f - wx);
    float w01 = (1.0f - wy) * wx;
    float w10 = wy * (1.0f - wx);
    float w11 = wy * wx;
    float acc = 0.0f;
    if (y0 >= 0 && y0 < HF_) {
        const float* rowp = g_imgT + ((size_t)(b * HF_ + y0) * WF_) * C_;
        if (x0 >= 0 && x0 < WF_) acc += w00 * rowp[(size_t)x0 * C_ + c];
        if (x1 >= 0 && x1 < WF_) acc += w01 * rowp[(size_t)x1 * C_ + c];
    }
    if (y1 >= 0 && y1 < HF_) {
        const float* rowp = g_imgT + ((size_t)(b * HF_ + y1) * WF_) * C_;
        if (x0 >= 0 && x0 < WF_) acc += w10 * rowp[(size_t)x0 * C_ + c];
        if (x1 >= 0 && x1 < WF_) acc += w11 * rowp[(size_t)x1 * C_ + c];
    }
    dst[c] = __float2half_rn(acc);
}

// ================= fp16 GEMM (ldmatrix + 3-stage cp.async, K-tile 32) =================
template<bool TB, bool HAS_BIAS, bool HAS_RES, bool RELU, bool OUT16>
__global__ __launch_bounds__(256, 2) void gemm_h(
    const __half* __restrict__ A, const __half* __restrict__ B,
    const float* __restrict__ bias, const float* __restrict__ Res,
    void* __restrict__ Cv,
    int M, int N, int K, int lda, int ldb, int ldc,
    long long sA, long long sB, long long sC, float alpha)
{
    extern __shared__ __half hsm[];
    __half* Asm = hsm;
    __half* Bsm = hsm + 3 * STG_HALVES_;

    long long z = blockIdx.z;
    A += z * sA; B += z * sB;
    float* Cf = (float*)Cv + (OUT16 ? 0 : z * sC);
    __half* Ch = (__half*)Cv + (OUT16 ? z * sC : 0);
    if (HAS_RES) Res += z * sC;

    int m0 = blockIdx.y * 128, n0 = blockIdx.x * 128;
    int t = threadIdx.x;
    int wid = t >> 5, lane = t & 31;
    int warp_m = wid >> 2;
    int warp_n = wid & 3;

    int l7 = lane & 7;
    int gidx = lane >> 3;

    uint32_t As_u = (uint32_t)__cvta_generic_to_shared(Asm);
    uint32_t Bs_u = (uint32_t)__cvta_generic_to_shared(Bsm);
    uint32_t a_lane  = (uint32_t)(((l7 + (gidx & 1) * 8) * 40 + (gidx >> 1) * 8) * 2);
    uint32_t bt_lane = a_lane;
    uint32_t bn_lane = (uint32_t)(((l7 + (gidx >> 1) * 8) * 136 + (gidx & 1) * 8) * 2);

    float acc[4][4][4];
#pragma unroll
    for (int i = 0; i < 4; i++)
#pragma unroll
        for (int j = 0; j < 4; j++)
#pragma unroll
            for (int r = 0; r < 4; r++) acc[i][j][r] = 0.0f;

    int KT = (K + 31) >> 5;

    auto load_tile = [&](int st, int k0) {
#pragma unroll
        for (int i = 0; i < 2; i++) {
            int lin = t + i * 256;
            int row = lin >> 2;
            int kc  = (lin & 3) * 8;
            int gm = m0 + row, gk = k0 + kc;
            cpa16(&Asm[st * STG_HALVES_ + row * 40 + kc],
                  A + (size_t)gm * lda + gk, gm < M && gk < K);
        }
        if (TB) {
#pragma unroll
            for (int i = 0; i < 2; i++) {
                int lin = t + i * 256;
                int row = lin >> 2;
                int kc  = (lin & 3) * 8;
                int gn = n0 + row, gk = k0 + kc;
                cpa16(&Bsm[st * STG_HALVES_ + row * 40 + kc],
                      B + (size_t)gn * ldb + gk, gn < N && gk < K);
            }
        } else {
#pragma unroll
            for (int i = 0; i < 2; i++) {
                int lin = t + i * 256;
                int kk = lin >> 4;
                int nc = (lin & 15) * 8;
                int gk = k0 + kk;
                cpa16(&Bsm[st * STG_HALVES_ + kk * 136 + nc],
                      B + (size_t)gk * ldb + n0 + nc, gk < K);
            }
        }
    };

    load_tile(0, 0); CPA_COMMIT();
    if (1 < KT) { load_tile(1, 32); CPA_COMMIT(); }

    for (int kt = 0; kt < KT; kt++) {
        if (kt + 1 < KT) { CPA_WAIT(1); } else { CPA_WAIT(0); }
        __syncthreads();
        if (kt + 2 < KT) { load_tile((kt + 2) % 3, (kt + 2) * 32); CPA_COMMIT(); }

        int st = kt % 3;
        uint32_t stoff = (uint32_t)(st * STG_HALVES_ * 2);
#pragma unroll
        for (int ks = 0; ks < 32; ks += 16) {
            uint32_t af[4][4];
#pragma unroll
            for (int mt = 0; mt < 4; mt++)
                ldsm4(af[mt], As_u + stoff +
                      (uint32_t)(((warp_m * 64 + mt * 16) * 40 + ks) * 2) + a_lane);
            uint32_t bf[4][2];
#pragma unroll
            for (int np = 0; np < 2; np++) {
                uint32_t tmp[4];
                if (TB) {
                    ldsm4(tmp, Bs_u + stoff +
                          (uint32_t)(((warp_n * 32 + np * 16) * 40 + ks) * 2) + bt_lane);
                } else {
                    ldsm4t(tmp, Bs_u + stoff +
                           (uint32_t)((ks * 136 + warp_n * 32 + np * 16) * 2) + bn_lane);
                }
                bf[2 * np][0]     = tmp[0]; bf[2 * np][1]     = tmp[2];
                bf[2 * np + 1][0] = tmp[1]; bf[2 * np + 1][1] = tmp[3];
            }
#pragma unroll
            for (int mt = 0; mt < 4; mt++)
#pragma unroll
                for (int nt = 0; nt < 4; nt++)
                    mma_f16(acc[mt][nt], af[mt], bf[nt]);
        }
    }

    // ---- epilogue ----
    int gq = lane >> 2, tq2 = lane & 3;
#pragma unroll
    for (int mt = 0; mt < 4; mt++) {
        int row0 = m0 + warp_m * 64 + mt * 16 + gq;
#pragma unroll
        for (int nt = 0; nt < 4; nt++) {
            int col = n0 + warp_n * 32 + nt * 8 + tq2 * 2;
#pragma unroll
            for (int half = 0; half < 2; half++) {
                int row = row0 + half * 8;
                if (row >= M) continue;
#pragma unroll
                for (int e = 0; e < 2; e++) {
                    int cc = col + e;
                    if (cc >= N) continue;
                    float v = acc[mt][nt][half * 2 + e] * alpha;
                    if (HAS_BIAS) v += bias[cc];
                    if (HAS_RES)  v += Res[(size_t)row * ldc + cc];
                    if (RELU)     v = fmaxf(v, 0.0f);
                    if (OUT16) Ch[(size_t)row * ldc + cc] = __float2half_rn(v);
                    else       Cf[(size_t)row * ldc + cc] = v;
                }
            }
        }
    }
}

// ================= fused GEMM + residual + LayerNorm =================
// Out = LN(A @ B^T + bias + Res) -> tgt fp32 + tgt_h fp16.
// M=8192 rows (block owns 64), N=256 (full width per block), B is (256,K) row-major.
// 8 warps as 1M x 8N (warp tile 64x32). K multiple of 32.
__global__ __launch_bounds__(256, 2) void gemm_ln(
    const __half* __restrict__ A, const __half* __restrict__ B,
    const float* __restrict__ bias, const float* __restrict__ Res,
    const float* __restrict__ lnw, const float* __restrict__ lnb,
    float* __restrict__ OutF, __half* __restrict__ OutH, int K)
{
    extern __shared__ __half hsm[];
    __half* Asm = hsm;                       // [3][64][40]
    __half* Bsm = hsm + 3 * LNA_H_;          // [3][256][40]
    float*  red = (float*)(hsm + 3 * (LNA_H_ + LNB_H_));
    float*  psum = red;                      // [8][64]
    float*  psq  = red + 512;                // [8][64]
    float*  smu  = red + 1024;               // [64]
    float*  srs  = red + 1088;               // [64]

    int m0 = blockIdx.x * 64;
    int t = threadIdx.x;
    int wid = t >> 5, lane = t & 31;
    int warp_n = wid;                        // 0..7
    int l7 = lane & 7;
    int gidx = lane >> 3;

    uint32_t As_u = (uint32_t)__cvta_generic_to_shared(Asm);
    uint32_t Bs_u = (uint32_t)__cvta_generic_to_shared(Bsm);
    uint32_t frag_lane = (uint32_t)(((l7 + (gidx & 1) * 8) * 40 + (gidx >> 1) * 8) * 2);

    float acc[4][4][4];
#pragma unroll
    for (int i = 0; i < 4; i++)
#pragma unroll
        for (int j = 0; j < 4; j++)
#pragma unroll
            for (int r = 0; r < 4; r++) acc[i][j][r] = 0.0f;

    int KT = K >> 5;

    auto load_tile = [&](int st, int k0) {
        {   // A: 64x32 halves = 256 chunks
            int row = t >> 2;
            int kc  = (t & 3) * 8;
            cpa16(&Asm[st * LNA_H_ + row * 40 + kc],
                  A + (size_t)(m0 + row) * K + k0 + kc, true);
        }
#pragma unroll
        for (int i = 0; i < 4; i++) {        // B: 256x32 halves = 1024 chunks
            int lin = t + i * 256;
            int row = lin >> 2;
            int kc  = (lin & 3) * 8;
            cpa16(&Bsm[st * LNB_H_ + row * 40 + kc],
                  B + (size_t)row * K + k0 + kc, true);
        }
    };

    load_tile(0, 0); CPA_COMMIT();
    if (1 < KT) { load_tile(1, 32); CPA_COMMIT(); }

    for (int kt = 0; kt < KT; kt++) {
        if (kt + 1 < KT) { CPA_WAIT(1); } else { CPA_WAIT(0); }
        __syncthreads();
        if (kt + 2 < KT) { load_tile((kt + 2) % 3, (kt + 2) * 32); CPA_COMMIT(); }

        int st = kt % 3;
#pragma unroll
        for (int ks = 0; ks < 32; ks += 16) {
            uint32_t af[4][4];
#pragma unroll
            for (int mt = 0; mt < 4; mt++)
                ldsm4(af[mt], As_u + (uint32_t)(st * LNA_H_ * 2) +
                      (uint32_t)((mt * 16 * 40 + ks) * 2) + frag_lane);
            uint32_t bf[4][2];
#pragma unroll
            for (int np = 0; np < 2; np++) {
                uint32_t tmp[4];
                ldsm4(tmp, Bs_u + (uint32_t)(st * LNB_H_ * 2) +
                      (uint32_t)(((warp_n * 32 + np * 16) * 40 + ks) * 2) + frag_lane);
                bf[2 * np][0]     = tmp[0]; bf[2 * np][1]     = tmp[2];
                bf[2 * np + 1][0] = tmp[1]; bf[2 * np + 1][1] = tmp[3];
            }
#pragma unroll
            for (int mt = 0; mt < 4; mt++)
#pragma unroll
                for (int nt = 0; nt < 4; nt++)
                    mma_f16(acc[mt][nt], af[mt], bf[nt]);
        }
    }

    // ---- epilogue: bias + residual, then LN over each full row ----
    int gq = lane >> 2, tq2 = lane & 3;
    // phase 1: finalize values in registers, per-row partials
#pragma unroll
    for (int mt = 0; mt < 4; mt++) {
#pragma unroll
        for (int half = 0; half < 2; half++) {
            int rl = mt * 16 + gq + half * 8;          // local row 0..63
            int grow = m0 + rl;
            float s8 = 0.0f, q8 = 0.0f;
#pragma unroll
            for (int nt = 0; nt < 4; nt++) {
#pragma unroll
                for (int e = 0; e < 2; e++) {
                    int cc = warp_n * 32 + nt * 8 + tq2 * 2 + e;
                    float v = acc[mt][nt][half * 2 + e] + bias[cc]
                            + Res[(size_t)grow * HID_ + cc];
                    acc[mt][nt][half * 2 + e] = v;
                    s8 += v;
                    q8 += v * v;
                }
            }
            // reduce across the 4 lanes (tq2) sharing this row within the warp
            s8 += __shfl_xor_sync(0xffffffffu, s8, 1);
            s8 += __shfl_xor_sync(0xffffffffu, s8, 2);
            q8 += __shfl_xor_sync(0xffffffffu, q8, 1);
            q8 += __shfl_xor_sync(0xffffffffu, q8, 2);
            if (tq2 == 0) {
                psum[wid * 64 + rl] = s8;
                psq [wid * 64 + rl] = q8;
            }
        }
    }
    __syncthreads();
    if (t < 64) {
        float s = 0.0f, q = 0.0f;
#pragma unroll
        for (int w = 0; w < 8; w++) { s += psum[w * 64 + t]; q += psq[w * 64 + t]; }
        float mu = s * (1.0f / 256.0f);
        float var = fmaxf(q * (1.0f / 256.0f) - mu * mu, 0.0f);
        smu[t] = mu;
        srs[t] = rsqrtf(var + LN_EPS_);
    }
    __syncthreads();
    // phase 3: normalized writes
#pragma unroll
    for (int mt = 0; mt < 4; mt++) {
#pragma unroll
        for (int half = 0; half < 2; half++) {
            int rl = mt * 16 + gq + half * 8;
            int grow = m0 + rl;
            float mu = smu[rl], rs = srs[rl];
#pragma unroll
            for (int nt = 0; nt < 4; nt++) {
#pragma unroll
                for (int e = 0; e < 2; e++) {
                    int cc = warp_n * 32 + nt * 8 + tq2 * 2 + e;
                    float o = (acc[mt][nt][half * 2 + e] - mu) * rs * lnw[cc] + lnb[cc];
                    OutF[(size_t)grow * HID_ + cc] = o;
                    OutH[(size_t)grow * HID_ + cc] = __float2half_rn(o);
                }
            }
        }
    }
}

// ---------------- tgt init ----------------
__global__ void init_tgt(const float* __restrict__ qe) {
    size_t i = (size_t)blockIdx.x * 256 + threadIdx.x;
    int c = (int)(i & 255);
    int q = (int)((i >> 8) & 15);
    float v = qe[q * HID_ + c];
    g_tgt[i] = v;
    g_tgt_h[i] = __float2half_rn(v);
}

// ---------------- self attention ----------------
__global__ __launch_bounds__(256) void self_attn() {
    int bn = blockIdx.x;
    __shared__ float sq[NQ_][260];
    __shared__ float sk[NQ_][260];
    __shared__ float sa[HEADS_][NQ_][NQ_ + 1];
    int t = threadIdx.x;
    const __half* base = g_qkv_h + (size_t)bn * NQ_ * 768;
    for (int i = t; i < NQ_ * HID_; i += 256) {
        int q = i >> 8, c = i & 255;
        sq[q][c] = __half2float(base[q * 768 + c]);
        sk[q][c] = __half2float(base[q * 768 + 256 + c]);
    }
    __syncthreads();
    const float scale = 0.17677669529663687f;
    for (int i = t; i < HEADS_ * NQ_ * NQ_; i += 256) {
        int h = i >> 8, q = (i >> 4) & 15, kk = i & 15;
        float acc = 0.0f;
#pragma unroll
        for (int d = 0; d < DH_; d++) acc += sq[q][h * DH_ + d] * sk[kk][h * DH_ + d];
        sa[h][q][kk] = acc * scale;
    }
    __syncthreads();
    if (t < HEADS_ * NQ_) {
        int h = t >> 4, q = t & 15;
        float m = -FLT_MAX;
#pragma unroll
        for (int kk = 0; kk < NQ_; kk++) m = fmaxf(m, sa[h][q][kk]);
        float s = 0.0f;
#pragma unroll
        for (int kk = 0; kk < NQ_; kk++) { float e = expf(sa[h][q][kk] - m); sa[h][q][kk] = e; s += e; }
        float inv = 1.0f / s;
#pragma unroll
        for (int kk = 0; kk < NQ_; kk++) sa[h][q][kk] *= inv;
    }
    __syncthreads();
    __half* out = g_ctx_h + (size_t)bn * NQ_ * HID_;
    for (int i = t; i < NQ_ * HID_; i += 256) {
        int q = i >> 8, c = i & 255;
        int h = c >> 5;
        float acc = 0.0f;
#pragma unroll
        for (int kk = 0; kk < NQ_; kk++)
            acc += sa[h][q][kk] * __half2float(base[kk * 768 + 512 + c]);
        out[q * HID_ + c] = __float2half_rn(acc);
    }
}

// ---------------- cross-attn U = Q_h @ Wk_h ----------------
__global__ __launch_bounds__(256) void cross_u(const float* __restrict__ Wk) {
    int h = blockIdx.x, bn = blockIdx.y;
    int c = threadIdx.x;
    __shared__ float sq[NQ_][DH_];
    for (int i = threadIdx.x; i < NQ_ * DH_; i += 256) {
        int q = i >> 5, d = i & 31;
        sq[q][d] = __half2float(g_qc_h[((size_t)bn * NQ_ + q) * HID_ + h * DH_ + d]);
    }
    __syncthreads();
    float acc[NQ_] = {};
#pragma unroll 4
    for (int d = 0; d < DH_; d++) {
        float w = Wk[(size_t)(h * DH_ + d) * HID_ + c];
#pragma unroll
        for (int q = 0; q < NQ_; q++) acc[q] += sq[q][d] * w;
    }
    __half* dst = g_uh + ((size_t)bn * 128 + h * NQ_) * HID_ + c;
#pragma unroll
    for (int q = 0; q < NQ_; q++) dst[(size_t)q * HID_] = __float2half_rn(acc[q]);
}

// ---------------- masked softmax, fp16 in-place in g_sh ----------------
__global__ __launch_bounds__(256) void softmax_cross() {
    int row = blockIdx.x * 8 + (threadIdx.x >> 5);
    int lane = threadIdx.x & 31;
    int bn = row >> 7;
    bool v = g_valid[bn] != 0;
    __half* s = g_sh + (size_t)row * SPAD_;
    float vals[8];
    float m = -FLT_MAX;
#pragma unroll
    for (int i = 0; i < 8; i++) {
        int k = lane + i * 32;
        bool active = (k < P2_) && (v || k == 0);
        float x = active ? __half2float(s[k]) : 0.0f;
        vals[i] = active ? x : -INFINITY;
        m = fmaxf(m, vals[i]);
    }
#pragma unroll
    for (int o = 16; o; o >>= 1) m = fmaxf(m, __shfl_xor_sync(0xffffffffu, m, o));
    float sum = 0.0f;
#pragma unroll
    for (int i = 0; i < 8; i++) {
        int k = lane + i * 32;
        bool active = (k < P2_) && (v || k == 0);
        float e = active ? expf(vals[i] - m) : 0.0f;
        vals[i] = e;
        sum += e;
    }
#pragma unroll
    for (int o = 16; o; o >>= 1) sum += __shfl_xor_sync(0xffffffffu, sum, o);
    float inv = 1.0f / sum;
#pragma unroll
    for (int i = 0; i < 8; i++) {
        int k = lane + i * 32;
        if (k < P2_)        s[k] = __float2half_rn(vals[i] * inv);
        else if (k < SPAD_) s[k] = __float2half_rn(0.0f);
    }
}

// ---------------- cross-attn output: ctx = T @ Wv_h^T + bv ----------------
__global__ __launch_bounds__(512) void cross_o(const float* __restrict__ Wv,
                                               const float* __restrict__ bv) {
    int h = blockIdx.x, bn = blockIdx.y;
    __shared__ float ws[DH_][HID_ + 1];
    int t = threadIdx.x;
    for (int i = t; i < DH_ * HID_; i += 512) {
        int d = i >> 8, c = i & 255;
        ws[d][c] = Wv[(size_t)(h * DH_ + d) * HID_ + c];
    }
    __syncthreads();
    int q = t >> 5, d = t & 31;
    const __half* trow = g_uh + ((size_t)bn * 128 + h * NQ_ + q) * HID_;
    float acc = 0.0f;
#pragma unroll 4
    for (int c = 0; c < HID_; c += 2) {
        __half2 hv = *reinterpret_cast<const __half2*>(trow + c);
        float2 f = __half22float2(hv);
        acc += f.x * ws[d][c] + f.y * ws[d][c + 1];
    }
    g_ctx_h[((size_t)bn * NQ_ + q) * HID_ + h * DH_ + d] = __float2half_rn(acc + bv[h * DH_ + d]);
}

// ---------------- final head ----------------
__global__ __launch_bounds__(256) void final_out(const float* __restrict__ W,
                                                 const float* __restrict__ bias,
                                                 float* __restrict__ out) {
    int row = blockIdx.x * 8 + (threadIdx.x >> 5);
    int lane = threadIdx.x & 31;
    const float* x = g_tgt + (size_t)row * HID_;
    float acc[4] = {};
#pragma unroll
    for (int i = 0; i < 8; i++) {
        int c = lane + i * 32;
        float xv = x[c];
#pragma unroll
        for (int j = 0; j < 4; j++) acc[j] += xv * W[j * HID_ + c];
    }
#pragma unroll
    for (int j = 0; j < 4; j++)
#pragma unroll
        for (int o = 16; o; o >>= 1) acc[j] += __shfl_xor_sync(0xffffffffu, acc[j], o);
    if (lane < 4) out[(size_t)row * 4 + lane] = acc[lane] + bias[lane];
}

// ---------------- host ----------------
extern "C" void kernel_launch(void* const* d_in, const int* in_sizes, int n_in,
                              void* d_out, int out_size) {
    (void)in_sizes; (void)n_in; (void)out_size;
    const float* img         = (const float*)d_in[0];
    const float* kp          = (const float*)d_in[1];
    const unsigned char* msk = (const unsigned char*)d_in[2];
    const float* proj_w      = (const float*)d_in[3];
    const float* proj_b      = (const float*)d_in[4];
    const float* query_embed = (const float*)d_in[5];
    const float* self_qkv_w  = (const float*)d_in[6];
    const float* self_qkv_b  = (const float*)d_in[7];
    const float* self_out_w  = (const float*)d_in[8];
    const float* self_out_b  = (const float*)d_in[9];
    const float* cross_qkv_w = (const float*)d_in[10];
    const float* cross_qkv_b = (const float*)d_in[11];
    const float* cross_out_w = (const float*)d_in[12];
    const float* cross_out_b = (const float*)d_in[13];
    const float* ffn1_w      = (const float*)d_in[14];
    const float* ffn1_b      = (const float*)d_in[15];
    const float* ffn2_w      = (const float*)d_in[16];
    const float* ffn2_b      = (const float*)d_in[17];
    const float* ln1_w       = (const float*)d_in[18];
    const float* ln1_b       = (const float*)d_in[19];
    const float* ln2_w       = (const float*)d_in[20];
    const float* ln2_b       = (const float*)d_in[21];
    const float* ln3_w       = (const float*)d_in[22];
    const float* ln3_b       = (const float*)d_in[23];
    const float* out_w       = (const float*)d_in[24];
    const float* out_b       = (const float*)d_in[25];
    float* out = (float*)d_out;

    float *tgt;
    unsigned char* valid;
    __half *feat_h, *mem_h, *tgt_h, *ctx_h, *qkv_h, *qc_h, *uh, *sh, *ffn_h;
    __half *projw_h, *sqkv_h, *sout_h, *cqkv_h, *cout_h, *f1_h, *f2_h;
    cudaGetSymbolAddress((void**)&tgt,   g_tgt);
    cudaGetSymbolAddress((void**)&valid, g_valid);
    cudaGetSymbolAddress((void**)&feat_h, g_feat_h);
    cudaGetSymbolAddress((void**)&mem_h,  g_mem_h);
    cudaGetSymbolAddress((void**)&tgt_h,  g_tgt_h);
    cudaGetSymbolAddress((void**)&ctx_h,  g_ctx_h);
    cudaGetSymbolAddress((void**)&qkv_h,  g_qkv_h);
    cudaGetSymbolAddress((void**)&qc_h,   g_qc_h);
    cudaGetSymbolAddress((void**)&uh,     g_uh);
    cudaGetSymbolAddress((void**)&sh,     g_sh);
    cudaGetSymbolAddress((void**)&ffn_h,  g_ffn_h);
    cudaGetSymbolAddress((void**)&projw_h, g_projw_h);
    cudaGetSymbolAddress((void**)&sqkv_h,  g_sqkv_h);
    cudaGetSymbolAddress((void**)&sout_h,  g_sout_h);
    cudaGetSymbolAddress((void**)&cqkv_h,  g_cqkv_h);
    cudaGetSymbolAddress((void**)&cout_h,  g_cout_h);
    cudaGetSymbolAddress((void**)&f1_h,    g_f1_h);
    cudaGetSymbolAddress((void**)&f2_h,    g_f2_h);

    cudaFuncSetAttribute((const void*)gemm_h<true,  true,  false, false, true>,
                         cudaFuncAttributeMaxDynamicSharedMemorySize, GEMM_SMEM_);
    cudaFuncSetAttribute((const void*)gemm_h<true,  false, false, false, true>,
                         cudaFuncAttributeMaxDynamicSharedMemorySize, GEMM_SMEM_);
    cudaFuncSetAttribute((const void*)gemm_h<false, false, false, false, true>,
                         cudaFuncAttributeMaxDynamicSharedMemorySize, GEMM_SMEM_);
    cudaFuncSetAttribute((const void*)gemm_h<true,  true,  false, true,  true>,
                         cudaFuncAttributeMaxDynamicSharedMemorySize, GEMM_SMEM_);
    cudaFuncSetAttribute((const void*)gemm_ln,
                         cudaFuncAttributeMaxDynamicSharedMemorySize, LN_SMEM_);

    const float scale = 0.17677669529663687f;

    decode_mask<<<1, 512>>>(msk, valid);
    { dim3 g(128, 8, B_); transpose_img<<<g, 256>>>(img); }
    { dim3 g(P2_, N_KP, B_); roi_gather<<<g, C_>>>(kp); }

    f2h_all<<<(WT_ + 255) / 256, 256>>>(proj_w, self_qkv_w, self_out_w,
                                        cross_qkv_w, cross_out_w, ffn1_w, ffn2_w);

    gemm_h<true, true, false, false, true><<<dim3(2, 900, 1), 256, GEMM_SMEM_>>>(
        feat_h, projw_h, proj_b, nullptr, mem_h, MMEM_, HID_, C_, C_, C_, HID_, 0, 0, 0, 1.0f);

    init_tgt<<<MROWS_, 256>>>(query_embed);

    for (int l = 0; l < DEPTH_; l++) {
        const __half* sW  = sqkv_h + (size_t)l * 3 * 65536;
        const float*  sB  = self_qkv_b  + (size_t)l * 3 * HID_;
        const __half* soW = sout_h + (size_t)l * 65536;
        const float*  soB = self_out_b  + (size_t)l * HID_;
        const __half* cWq = cqkv_h + (size_t)l * 3 * 65536;
        const float*  cB  = cross_qkv_b + (size_t)l * 3 * HID_;
        const float*  cWf = cross_qkv_w + (size_t)l * 3 * HID_ * HID_;
        const __half* coW = cout_h + (size_t)l * 65536;
        const float*  coB = cross_out_b + (size_t)l * HID_;
        const __half* f1W = f1_h + (size_t)l * 262144;
        const float*  f1B = ffn1_b + (size_t)l * FFN_;
        const __half* f2W = f2_h + (size_t)l * 262144;
        const float*  f2B = ffn2_b + (size_t)l * HID_;

        // --- self attention ---
        gemm_h<true, true, false, false, true><<<dim3(6, 64, 1), 256, GEMM_SMEM_>>>(
            tgt_h, sW, sB, nullptr, qkv_h, MROWS_, 3 * HID_, HID_, HID_, HID_, 3 * HID_, 0, 0, 0, 1.0f);
        self_attn<<<BN_, 256>>>();
        gemm_ln<<<128, 256, LN_SMEM_>>>(ctx_h, soW, soB, tgt,
                                        ln1_w + l * HID_, ln1_b + l * HID_, tgt, tgt_h, HID_);

        // --- cross attention (factored K/V) ---
        gemm_h<true, true, false, false, true><<<dim3(2, 64, 1), 256, GEMM_SMEM_>>>(
            tgt_h, cWq, cB, nullptr, qc_h, MROWS_, HID_, HID_, HID_, HID_, HID_, 0, 0, 0, 1.0f);
        { dim3 g(HEADS_, BN_); cross_u<<<g, 256>>>(cWf + (size_t)HID_ * HID_); }
        gemm_h<true, false, false, false, true><<<dim3(2, 1, BN_), 256, GEMM_SMEM_>>>(
            uh, mem_h, nullptr, nullptr, sh, 128, P2_, HID_, HID_, HID_, SPAD_,
            (long long)128 * HID_, (long long)P2_ * HID_, (long long)128 * SPAD_, scale);
        softmax_cross<<<(BN_ * 128) / 8, 256>>>();
        gemm_h<false, false, false, false, true><<<dim3(2, 1, BN_), 256, GEMM_SMEM_>>>(
            sh, mem_h, nullptr, nullptr, uh, 128, HID_, P2_, SPAD_, HID_, HID_,
            (long long)128 * SPAD_, (long long)P2_ * HID_, (long long)128 * HID_, 1.0f);
        { dim3 g(HEADS_, BN_); cross_o<<<g, 512>>>(cWf + (size_t)2 * HID_ * HID_, cB + 2 * HID_); }
        gemm_ln<<<128, 256, LN_SMEM_>>>(ctx_h, coW, coB, tgt,
                                        ln2_w + l * HID_, ln2_b + l * HID_, tgt, tgt_h, HID_);

        // --- FFN ---
        gemm_h<true, true, false, true, true><<<dim3(8, 64, 1), 256, GEMM_SMEM_>>>(
            tgt_h, f1W, f1B, nullptr, ffn_h, MROWS_, FFN_, HID_, HID_, HID_, FFN_, 0, 0, 0, 1.0f);
        gemm_ln<<<128, 256, LN_SMEM_>>>(ffn_h, f2W, f2B, tgt,
                                        ln3_w + l * HID_, ln3_b + l * HID_, tgt, tgt_h, FFN_);
    }

    final_out<<<MROWS_ / 8, 256>>>(out_w, out_b, out);
}

// round 17
// speedup vs baseline: 1.0781x; 1.0531x over previous
#include <cuda_runtime.h>
#include <cuda_fp16.h>
#include <math.h>
#include <float.h>
#include <stdint.h>

#define B_      2
#define N_KP    256
#define C_      256
#define HF_     64
#define WF_     64
#define ROI_    15
#define P2_     225
#define HID_    256
#define HEADS_  8
#define DH_     32
#define DEPTH_  3
#define FFN_    1024
#define NQ_     16
#define BN_     512
#define MROWS_  8192
#define MMEM_   115200
#define LN_EPS_ 1e-5f

#define STG_HALVES_ 5120
#define GEMM_SMEM_  (3 * 2 * STG_HALVES_ * 2)    // 61440 B
#define LNA_H_   2560
#define LNB_H_   10240
#define LN_SMEM_ (3 * (LNA_H_ + LNB_H_) * 2 + 4608)   // 81408 B
// attn_fused: 2 stages x (A 5120 + B 5120) halves + S 128x264 halves
#define SSTRIDE_ 264
#define ATTN_SMEM_ ((2 * 10240 + 128 * SSTRIDE_) * 2)  // 108544 B

// ---------------- scratch ----------------
__device__ float g_imgT[(size_t)B_ * HF_ * WF_ * C_];
__device__ float g_tgt [(size_t)MROWS_ * HID_];
__device__ unsigned char g_valid[BN_];

// fp16 activations
__device__ __half g_feat_h[(size_t)MMEM_ * C_];
__device__ __half g_mem_h [(size_t)MMEM_ * C_];
__device__ __half g_tgt_h [(size_t)MROWS_ * HID_];
__device__ __half g_ctx_h [(size_t)MROWS_ * HID_];
__device__ __half g_qkv4_h[(size_t)MROWS_ * 1024];     // q|k|v|qc
__device__ __half g_uh    [(size_t)BN_ * 128 * HID_];  // U, then T
__device__ __half g_ffn_h [(size_t)MROWS_ * FFN_];
// fp16 weights
__device__ __half g_projw_h[65536];
__device__ __half g_sout_h [3 * 65536];
__device__ __half g_cout_h [3 * 65536];
__device__ __half g_f1_h   [3 * 262144];
__device__ __half g_f2_h   [3 * 262144];
__device__ __half g_qkv4w_h[3 * 1024 * 256];
__device__ float  g_qkv4b  [3 * 1024];

// ---------------- helpers ----------------
__device__ __forceinline__ void mma_f16(float* c, const uint32_t* a, const uint32_t* b) {
    asm volatile(
        "mma.sync.aligned.m16n8k16.row.col.f32.f16.f16.f32 "
        "{%0,%1,%2,%3}, {%4,%5,%6,%7}, {%8,%9}, {%0,%1,%2,%3};\n"
        : "+f"(c[0]), "+f"(c[1]), "+f"(c[2]), "+f"(c[3])
        : "r"(a[0]), "r"(a[1]), "r"(a[2]), "r"(a[3]), "r"(b[0]), "r"(b[1]));
}
__device__ __forceinline__ void ldsm4(uint32_t* r, uint32_t saddr) {
    asm volatile("ldmatrix.sync.aligned.m8n8.x4.shared.b16 {%0,%1,%2,%3}, [%4];\n"
                 : "=r"(r[0]), "=r"(r[1]), "=r"(r[2]), "=r"(r[3]) : "r"(saddr));
}
__device__ __forceinline__ void ldsm4t(uint32_t* r, uint32_t saddr) {
    asm volatile("ldmatrix.sync.aligned.m8n8.x4.trans.shared.b16 {%0,%1,%2,%3}, [%4];\n"
                 : "=r"(r[0]), "=r"(r[1]), "=r"(r[2]), "=r"(r[3]) : "r"(saddr));
}
__device__ __forceinline__ void cpa16(void* smem_ptr, const void* gptr, bool pred) {
    uint32_t sa = (uint32_t)__cvta_generic_to_shared(smem_ptr);
    int sz = pred ? 16 : 0;
    asm volatile("cp.async.cg.shared.global [%0], [%1], 16, %2;\n"
                 :: "r"(sa), "l"(gptr), "r"(sz));
}
#define CPA_COMMIT() asm volatile("cp.async.commit_group;\n")
#define CPA_WAIT(n)  asm volatile("cp.async.wait_group %0;\n" :: "n"(n))

// ---------------- weight converts ----------------
#define W0_ 65536
#define W2_ 196608
#define W4_ 196608
#define W5_ 786432
#define W6_ 786432
#define WT_ (W0_+W2_+W4_+W5_+W6_)

__global__ void f2h_all(const float* __restrict__ p0, const float* __restrict__ p2,
                        const float* __restrict__ p4, const float* __restrict__ p5,
                        const float* __restrict__ p6) {
    long i = (long)blockIdx.x * 256 + threadIdx.x;
    if (i >= WT_) return;
    long o = i;
    if (o < W0_) { g_projw_h[o] = __float2half_rn(p0[o]); return; } o -= W0_;
    if (o < W2_) { g_sout_h[o]  = __float2half_rn(p2[o]); return; } o -= W2_;
    if (o < W4_) { g_cout_h[o]  = __float2half_rn(p4[o]); return; } o -= W4_;
    if (o < W5_) { g_f1_h[o]    = __float2half_rn(p5[o]); return; } o -= W5_;
    g_f2_h[o] = __float2half_rn(p6[o]);
}

// pack [self_qkv_w (768); cross_Wq (256)] + biases, per layer
__global__ void pack_qkv4(const float* __restrict__ sW, const float* __restrict__ cW,
                          const float* __restrict__ sB, const float* __restrict__ cB) {
    long i = (long)blockIdx.x * 256 + threadIdx.x;
    if (i >= 3L * 1024 * 256) return;
    int l = (int)(i / (1024 * 256));
    int r = (int)((i / 256) % 1024);
    int c = (int)(i % 256);
    float w = (r < 768) ? sW[(size_t)l * 768 * 256 + r * 256 + c]
                        : cW[(size_t)l * 768 * 256 + (r - 768) * 256 + c];
    g_qkv4w_h[i] = __float2half_rn(w);
    if (c == 0) {
        float b = (r < 768) ? sB[l * 768 + r] : cB[l * 768 + (r - 768)];
        g_qkv4b[l * 1024 + r] = b;
    }
}

__global__ void decode_mask(const unsigned char* __restrict__ m, unsigned char* __restrict__ out) {
    __shared__ int flag;
    if (threadIdx.x == 0) flag = 0;
    __syncthreads();
    int i = threadIdx.x;
    unsigned char v8 = m[i];
    if ((i & 3) != 0 && v8 != 0) atomicOr(&flag, 1);
    __syncthreads();
    if (flag) out[i] = (v8 != 0);
    else      out[i] = (((const int*)m)[i] != 0);
}

// ---------------- coalesced image transpose ----------------
__global__ __launch_bounds__(256) void transpose_img(const float* __restrict__ img) {
    __shared__ float tile[32][33];
    int b = blockIdx.z;
    int s0 = blockIdx.x * 32;
    int c0 = blockIdx.y * 32;
    int t = threadIdx.x;
    int tx = t & 31;
    int r0 = t >> 5;
    const float* src = img + (size_t)b * C_ * 4096;
#pragma unroll
    for (int p = 0; p < 4; p++) {
        int i = r0 + p * 8;
        tile[i][tx] = src[(size_t)(c0 + i) * 4096 + s0 + tx];
    }
    __syncthreads();
    float* dst = g_imgT + (size_t)b * 4096 * C_;
#pragma unroll
    for (int p = 0; p < 4; p++) {
        int i = r0 + p * 8;
        dst[(size_t)(s0 + i) * C_ + c0 + tx] = tile[tx][i];
    }
}

// ---------------- ROI bilinear gather -> fp16 feat ----------------
__global__ __launch_bounds__(256) void roi_gather(const float* __restrict__ kp) {
    int p = blockIdx.x, n = blockIdx.y, b = blockIdx.z, c = threadIdx.x;
    int iy = p / ROI_, ix = p % ROI_;
    float rc0 = rintf(kp[((size_t)b * N_KP + n) * 2 + 0]);
    float rc1 = rintf(kp[((size_t)b * N_KP + n) * 2 + 1]);
    float gy = rc0 + (float)(iy - 7);
    float gx = rc1 + (float)(ix - 7);
    float gxn = __fdiv_rn(gx, 511.0f) * 2.0f - 1.0f;
    float gyn = __fdiv_rn(gy, 511.0f) * 2.0f - 1.0f;
    bool invalid = (gxn < -1.0f) || (gyn < -1.0f) || (gxn > 1.0f) || (gyn > 1.0f);
    __half* dst = g_feat_h + ((size_t)((b * N_KP + n) * P2_ + p)) * C_;
    if (invalid) { dst[c] = __float2half_rn(0.0f); return; }
    float x = ((gxn + 1.0f) * (float)WF_ - 1.0f) * 0.5f;
    float y = ((gyn + 1.0f) * (float)HF_ - 1.0f) * 0.5f;
    float x0f = floorf(x), y0f = floorf(y);
    float wx = x - x0f, wy = y - y0f;
    int x0 = (int)x0f, y0 = (int)y0f;
    int x1 = x0 + 1, y1 = y0 + 1;
    float w00 = (1.0f - wy) * (1.0f - wx);
    float w01 = (1.0f - wy) * wx;
    float w10 = wy * (1.0f - wx);
    float w11 = wy * wx;
    float acc = 0.0f;
    if (y0 >= 0 && y0 < HF_) {
        const float* rowp = g_imgT + ((size_t)(b * HF_ + y0) * WF_) * C_;
        if (x0 >= 0 && x0 < WF_) acc += w00 * rowp[(size_t)x0 * C_ + c];
        if (x1 >= 0 && x1 < WF_) acc += w01 * rowp[(size_t)x1 * C_ + c];
    }
    if (y1 >= 0 && y1 < HF_) {
        const float* rowp = g_imgT + ((size_t)(b * HF_ + y1) * WF_) * C_;
        if (x0 >= 0 && x0 < WF_) acc += w10 * rowp[(size_t)x0 * C_ + c];
        if (x1 >= 0 && x1 < WF_) acc += w11 * rowp[(size_t)x1 * C_ + c];
    }
    dst[c] = __float2half_rn(acc);
}

// ================= fp16 GEMM (ldmatrix + 3-stage cp.async, K-tile 32) =================
// C = A @ B^T + bias [relu]; fp16 out. B is (N,K) row-major.
template<bool RELU>
__global__ __launch_bounds__(256, 2) void gemm_h(
    const __half* __restrict__ A, const __half* __restrict__ B,
    const float* __restrict__ bias, __half* __restrict__ Ch,
    int M, int N, int K, int lda, int ldb, int ldc)
{
    extern __shared__ __half hsm[];
    __half* Asm = hsm;
    __half* Bsm = hsm + 3 * STG_HALVES_;

    int m0 = blockIdx.y * 128, n0 = blockIdx.x * 128;
    int t = threadIdx.x;
    int wid = t >> 5, lane = t & 31;
    int warp_m = wid >> 2;
    int warp_n = wid & 3;
    int l7 = lane & 7;
    int gidx = lane >> 3;

    uint32_t As_u = (uint32_t)__cvta_generic_to_shared(Asm);
    uint32_t Bs_u = (uint32_t)__cvta_generic_to_shared(Bsm);
    uint32_t a_lane = (uint32_t)(((l7 + (gidx & 1) * 8) * 40 + (gidx >> 1) * 8) * 2);

    float acc[4][4][4];
#pragma unroll
    for (int i = 0; i < 4; i++)
#pragma unroll
        for (int j = 0; j < 4; j++)
#pragma unroll
            for (int r = 0; r < 4; r++) acc[i][j][r] = 0.0f;

    int KT = (K + 31) >> 5;

    auto load_tile = [&](int st, int k0) {
#pragma unroll
        for (int i = 0; i < 2; i++) {
            int lin = t + i * 256;
            int row = lin >> 2;
            int kc  = (lin & 3) * 8;
            int gm = m0 + row, gk = k0 + kc;
            cpa16(&Asm[st * STG_HALVES_ + row * 40 + kc],
                  A + (size_t)gm * lda + gk, gm < M && gk < K);
        }
#pragma unroll
        for (int i = 0; i < 2; i++) {
            int lin = t + i * 256;
            int row = lin >> 2;
            int kc  = (lin & 3) * 8;
            int gn = n0 + row, gk = k0 + kc;
            cpa16(&Bsm[st * STG_HALVES_ + row * 40 + kc],
                  B + (size_t)gn * ldb + gk, gn < N && gk < K);
        }
    };

    load_tile(0, 0); CPA_COMMIT();
    if (1 < KT) { load_tile(1, 32); CPA_COMMIT(); }

    for (int kt = 0; kt < KT; kt++) {
        if (kt + 1 < KT) { CPA_WAIT(1); } else { CPA_WAIT(0); }
        __syncthreads();
        if (kt + 2 < KT) { load_tile((kt + 2) % 3, (kt + 2) * 32); CPA_COMMIT(); }

        int st = kt % 3;
        uint32_t stoff = (uint32_t)(st * STG_HALVES_ * 2);
#pragma unroll
        for (int ks = 0; ks < 32; ks += 16) {
            uint32_t af[4][4];
#pragma unroll
            for (int mt = 0; mt < 4; mt++)
                ldsm4(af[mt], As_u + stoff +
                      (uint32_t)(((warp_m * 64 + mt * 16) * 40 + ks) * 2) + a_lane);
            uint32_t bf[4][2];
#pragma unroll
            for (int np = 0; np < 2; np++) {
                uint32_t tmp[4];
                ldsm4(tmp, Bs_u + stoff +
                      (uint32_t)(((warp_n * 32 + np * 16) * 40 + ks) * 2) + a_lane);
                bf[2 * np][0]     = tmp[0]; bf[2 * np][1]     = tmp[2];
                bf[2 * np + 1][0] = tmp[1]; bf[2 * np + 1][1] = tmp[3];
            }
#pragma unroll
            for (int mt = 0; mt < 4; mt++)
#pragma unroll
                for (int nt = 0; nt < 4; nt++)
                    mma_f16(acc[mt][nt], af[mt], bf[nt]);
        }
    }

    int gq = lane >> 2, tq2 = lane & 3;
#pragma unroll
    for (int mt = 0; mt < 4; mt++) {
        int row0 = m0 + warp_m * 64 + mt * 16 + gq;
#pragma unroll
        for (int nt = 0; nt < 4; nt++) {
            int col = n0 + warp_n * 32 + nt * 8 + tq2 * 2;
#pragma unroll
            for (int half = 0; half < 2; half++) {
                int row = row0 + half * 8;
                if (row >= M) continue;
#pragma unroll
                for (int e = 0; e < 2; e++) {
                    int cc = col + e;
                    if (cc >= N) continue;
                    float v = acc[mt][nt][half * 2 + e] + bias[cc];
                    if (RELU) v = fmaxf(v, 0.0f);
                    Ch[(size_t)row * ldc + cc] = __float2half_rn(v);
                }
            }
        }
    }
}

// ================= fused GEMM + residual + LayerNorm =================
__global__ __launch_bounds__(256, 2) void gemm_ln(
    const __half* __restrict__ A, const __half* __restrict__ B,
    const float* __restrict__ bias, const float* __restrict__ Res,
    const float* __restrict__ lnw, const float* __restrict__ lnb,
    float* __restrict__ OutF, __half* __restrict__ OutH, int K)
{
    extern __shared__ __half hsm[];
    __half* Asm = hsm;
    __half* Bsm = hsm + 3 * LNA_H_;
    float*  red = (float*)(hsm + 3 * (LNA_H_ + LNB_H_));
    float*  psum = red;
    float*  psq  = red + 512;
    float*  smu  = red + 1024;
    float*  srs  = red + 1088;

    int m0 = blockIdx.x * 64;
    int t = threadIdx.x;
    int wid = t >> 5, lane = t & 31;
    int warp_n = wid;
    int l7 = lane & 7;
    int gidx = lane >> 3;

    uint32_t As_u = (uint32_t)__cvta_generic_to_shared(Asm);
    uint32_t Bs_u = (uint32_t)__cvta_generic_to_shared(Bsm);
    uint32_t frag_lane = (uint32_t)(((l7 + (gidx & 1) * 8) * 40 + (gidx >> 1) * 8) * 2);

    float acc[4][4][4];
#pragma unroll
    for (int i = 0; i < 4; i++)
#pragma unroll
        for (int j = 0; j < 4; j++)
#pragma unroll
            for (int r = 0; r < 4; r++) acc[i][j][r] = 0.0f;

    int KT = K >> 5;

    auto load_tile = [&](int st, int k0) {
        {
            int row = t >> 2;
            int kc  = (t & 3) * 8;
            cpa16(&Asm[st * LNA_H_ + row * 40 + kc],
                  A + (size_t)(m0 + row) * K + k0 + kc, true);
        }
#pragma unroll
        for (int i = 0; i < 4; i++) {
            int lin = t + i * 256;
            int row = lin >> 2;
            int kc  = (lin & 3) * 8;
            cpa16(&Bsm[st * LNB_H_ + row * 40 + kc],
                  B + (size_t)row * K + k0 + kc, true);
        }
    };

    load_tile(0, 0); CPA_COMMIT();
    if (1 < KT) { load_tile(1, 32); CPA_COMMIT(); }

    for (int kt = 0; kt < KT; kt++) {
        if (kt + 1 < KT) { CPA_WAIT(1); } else { CPA_WAIT(0); }
        __syncthreads();
        if (kt + 2 < KT) { load_tile((kt + 2) % 3, (kt + 2) * 32); CPA_COMMIT(); }

        int st = kt % 3;
#pragma unroll
        for (int ks = 0; ks < 32; ks += 16) {
            uint32_t af[4][4];
#pragma unroll
            for (int mt = 0; mt < 4; mt++)
                ldsm4(af[mt], As_u + (uint32_t)(st * LNA_H_ * 2) +
                      (uint32_t)((mt * 16 * 40 + ks) * 2) + frag_lane);
            uint32_t bf[4][2];
#pragma unroll
            for (int np = 0; np < 2; np++) {
                uint32_t tmp[4];
                ldsm4(tmp, Bs_u + (uint32_t)(st * LNB_H_ * 2) +
                      (uint32_t)(((warp_n * 32 + np * 16) * 40 + ks) * 2) + frag_lane);
                bf[2 * np][0]     = tmp[0]; bf[2 * np][1]     = tmp[2];
                bf[2 * np + 1][0] = tmp[1]; bf[2 * np + 1][1] = tmp[3];
            }
#pragma unroll
            for (int mt = 0; mt < 4; mt++)
#pragma unroll
                for (int nt = 0; nt < 4; nt++)
                    mma_f16(acc[mt][nt], af[mt], bf[nt]);
        }
    }

    int gq = lane >> 2, tq2 = lane & 3;
#pragma unroll
    for (int mt = 0; mt < 4; mt++) {
#pragma unroll
        for (int half = 0; half < 2; half++) {
            int rl = mt * 16 + gq + half * 8;
            int grow = m0 + rl;
            float s8 = 0.0f, q8 = 0.0f;
#pragma unroll
            for (int nt = 0; nt < 4; nt++) {
#pragma unroll
                for (int e = 0; e < 2; e++) {
                    int cc = warp_n * 32 + nt * 8 + tq2 * 2 + e;
                    float v = acc[mt][nt][half * 2 + e] + bias[cc]
                            + Res[(size_t)grow * HID_ + cc];
                    acc[mt][nt][half * 2 + e] = v;
                    s8 += v;
                    q8 += v * v;
                }
            }
            s8 += __shfl_xor_sync(0xffffffffu, s8, 1);
            s8 += __shfl_xor_sync(0xffffffffu, s8, 2);
            q8 += __shfl_xor_sync(0xffffffffu, q8, 1);
            q8 += __shfl_xor_sync(0xffffffffu, q8, 2);
            if (tq2 == 0) {
                psum[wid * 64 + rl] = s8;
                psq [wid * 64 + rl] = q8;
            }
        }
    }
    __syncthreads();
    if (t < 64) {
        float s = 0.0f, q = 0.0f;
#pragma unroll
        for (int w = 0; w < 8; w++) { s += psum[w * 64 + t]; q += psq[w * 64 + t]; }
        float mu = s * (1.0f / 256.0f);
        float var = fmaxf(q * (1.0f / 256.0f) - mu * mu, 0.0f);
        smu[t] = mu;
        srs[t] = rsqrtf(var + LN_EPS_);
    }
    __syncthreads();
#pragma unroll
    for (int mt = 0; mt < 4; mt++) {
#pragma unroll
        for (int half = 0; half < 2; half++) {
            int rl = mt * 16 + gq + half * 8;
            int grow = m0 + rl;
            float mu = smu[rl], rs = srs[rl];
#pragma unroll
            for (int nt = 0; nt < 4; nt++) {
#pragma unroll
                for (int e = 0; e < 2; e++) {
                    int cc = warp_n * 32 + nt * 8 + tq2 * 2 + e;
                    float o = (acc[mt][nt][half * 2 + e] - mu) * rs * lnw[cc] + lnb[cc];
                    OutF[(size_t)grow * HID_ + cc] = o;
                    OutH[(size_t)grow * HID_ + cc] = __float2half_rn(o);
                }
            }
        }
    }
}

// ================= fused cross-attn: S = scale*U@mem^T -> softmax -> T = A@mem =================
// One block per bn (512 blocks, 256 threads). 2-stage cp.async, S resident fp16 smem.
__global__ __launch_bounds__(256) void attn_fused() {
    extern __shared__ __half hsm[];
    __half* Astg = hsm;                    // [2][5120]: stage s at s*10240
    __half* Bstg = hsm + 5120;             // [2][5120]: stage s at s*10240+5120
    __half* Ssm  = hsm + 20480;            // [128][SSTRIDE_]
#define STG_A(s)  (Astg + (s) * 10240)
#define STG_B(s)  (Bstg + (s) * 10240)

    int bn = blockIdx.x;
    int t = threadIdx.x;
    int wid = t >> 5, lane = t & 31;
    int warp_m = wid >> 2;
    int warp_n = wid & 3;
    int l7 = lane & 7;
    int gidx = lane >> 3;
    int gq = lane >> 2, tq2 = lane & 3;
    const float scale = 0.17677669529663687f;

    const __half* U   = g_uh    + (size_t)bn * 128 * HID_;
    const __half* Mem = g_mem_h + (size_t)bn * P2_ * HID_;

    uint32_t stgA_u = (uint32_t)__cvta_generic_to_shared(Astg);
    uint32_t stgB_u = (uint32_t)__cvta_generic_to_shared(Bstg);
    uint32_t S_u    = (uint32_t)__cvta_generic_to_shared(Ssm);
    uint32_t a40    = (uint32_t)(((l7 + (gidx & 1) * 8) * 40 + (gidx >> 1) * 8) * 2);
    uint32_t aS     = (uint32_t)(((l7 + (gidx & 1) * 8) * SSTRIDE_ + (gidx >> 1) * 8) * 2);
    uint32_t bn_ld  = (uint32_t)(((l7 + (gidx >> 1) * 8) * 136 + (gidx & 1) * 8) * 2);

    float acc[4][4][4];

    // ===== phase S: two 128-col chunks =====
    for (int nc = 0; nc < 2; nc++) {
        int n0 = nc * 128;
#pragma unroll
        for (int i = 0; i < 4; i++)
#pragma unroll
            for (int j = 0; j < 4; j++)
#pragma unroll
                for (int r = 0; r < 4; r++) acc[i][j][r] = 0.0f;

        auto loadS = [&](int st, int k0) {
#pragma unroll
            for (int i = 0; i < 2; i++) {
                int lin = t + i * 256;
                int row = lin >> 2;
                int kc  = (lin & 3) * 8;
                cpa16(STG_A(st) + row * 40 + kc, U + (size_t)row * HID_ + k0 + kc, true);
                cpa16(STG_B(st) + row * 40 + kc,
                      Mem + (size_t)(n0 + row) * HID_ + k0 + kc, n0 + row < P2_);
            }
        };

        loadS(0, 0); CPA_COMMIT();
        for (int kt = 0; kt < 8; kt++) {
            if (kt + 1 < 8) { loadS((kt + 1) & 1, (kt + 1) * 32); CPA_COMMIT(); CPA_WAIT(1); }
            else            { CPA_WAIT(0); }
            __syncthreads();
            int st = kt & 1;
#pragma unroll
            for (int ks = 0; ks < 32; ks += 16) {
                uint32_t af[4][4];
#pragma unroll
                for (int mt = 0; mt < 4; mt++)
                    ldsm4(af[mt], stgA_u + (uint32_t)(st * 10240 * 2) +
                          (uint32_t)(((warp_m * 64 + mt * 16) * 40 + ks) * 2) + a40);
                uint32_t bf[4][2];
#pragma unroll
                for (int np = 0; np < 2; np++) {
                    uint32_t tmp[4];
                    ldsm4(tmp, stgB_u + (uint32_t)(st * 10240 * 2) +
                          (uint32_t)(((warp_n * 32 + np * 16) * 40 + ks) * 2) + a40);
                    bf[2 * np][0]     = tmp[0]; bf[2 * np][1]     = tmp[2];
                    bf[2 * np + 1][0] = tmp[1]; bf[2 * np + 1][1] = tmp[3];
                }
#pragma unroll
                for (int mt = 0; mt < 4; mt++)
#pragma unroll
                    for (int nt = 0; nt < 4; nt++)
                        mma_f16(acc[mt][nt], af[mt], bf[nt]);
            }
            __syncthreads();
        }
        // write S chunk to smem (fp16, scaled)
#pragma unroll
        for (int mt = 0; mt < 4; mt++) {
#pragma unroll
            for (int half = 0; half < 2; half++) {
                int row = warp_m * 64 + mt * 16 + gq + half * 8;
#pragma unroll
                for (int nt = 0; nt < 4; nt++) {
#pragma unroll
                    for (int e = 0; e < 2; e++) {
                        int col = n0 + warp_n * 32 + nt * 8 + tq2 * 2 + e;
                        Ssm[row * SSTRIDE_ + col] =
                            __float2half_rn(acc[mt][nt][half * 2 + e] * scale);
                    }
                }
            }
        }
    }
    __syncthreads();

    // ===== softmax in smem: warp wid handles rows wid*16..+15 =====
    bool v = g_valid[bn] != 0;
    for (int rr = 0; rr < 16; rr++) {
        int row = wid * 16 + rr;
        __half* srow = Ssm + row * SSTRIDE_;
        float vals[8];
        float m = -FLT_MAX;
#pragma unroll
        for (int i = 0; i < 8; i++) {
            int k = lane + i * 32;
            bool active = (k < P2_) && (v || k == 0);
            float x = active ? __half2float(srow[k]) : 0.0f;
            vals[i] = active ? x : -INFINITY;
            m = fmaxf(m, vals[i]);
        }
#pragma unroll
        for (int o = 16; o; o >>= 1) m = fmaxf(m, __shfl_xor_sync(0xffffffffu, m, o));
        float sum = 0.0f;
#pragma unroll
        for (int i = 0; i < 8; i++) {
            int k = lane + i * 32;
            bool active = (k < P2_) && (v || k == 0);
            float e = active ? expf(vals[i] - m) : 0.0f;
            vals[i] = e;
            sum += e;
        }
#pragma unroll
        for (int o = 16; o; o >>= 1) sum += __shfl_xor_sync(0xffffffffu, sum, o);
        float inv = 1.0f / sum;
#pragma unroll
        for (int i = 0; i < 8; i++) {
            int k = lane + i * 32;
            if (k < P2_) srow[k] = __float2half_rn(vals[i] * inv);
            else         srow[k] = __float2half_rn(0.0f);   // k in [225,256)
        }
    }
    __syncthreads();

    // ===== phase T: T = A(S, smem) @ mem, two 128-col chunks, write over g_uh =====
    __half* Tout = g_uh + (size_t)bn * 128 * HID_;
    for (int nc = 0; nc < 2; nc++) {
        int n0 = nc * 128;
#pragma unroll
        for (int i = 0; i < 4; i++)
#pragma unroll
            for (int j = 0; j < 4; j++)
#pragma unroll
                for (int r = 0; r < 4; r++) acc[i][j][r] = 0.0f;

        auto loadT = [&](int st, int k0) {
#pragma unroll
            for (int i = 0; i < 2; i++) {
                int lin = t + i * 256;
                int kk = lin >> 4;              // 0..31
                int c8 = (lin & 15) * 8;        // 0..120
                int gk = k0 + kk;
                cpa16(STG_B(st) + kk * 136 + c8,
                      Mem + (size_t)gk * HID_ + n0 + c8, gk < P2_);
            }
        };

        loadT(0, 0); CPA_COMMIT();
        for (int kt = 0; kt < 8; kt++) {
            if (kt + 1 < 8) { loadT((kt + 1) & 1, (kt + 1) * 32); CPA_COMMIT(); CPA_WAIT(1); }
            else            { CPA_WAIT(0); }
            __syncthreads();
            int st = kt & 1;
            int kg = kt * 32;
#pragma unroll
            for (int ks = 0; ks < 32; ks += 16) {
                uint32_t af[4][4];
#pragma unroll
                for (int mt = 0; mt < 4; mt++)
                    ldsm4(af[mt], S_u +
                          (uint32_t)(((warp_m * 64 + mt * 16) * SSTRIDE_ + kg + ks) * 2) + aS);
                uint32_t bf[4][2];
#pragma unroll
                for (int np = 0; np < 2; np++) {
                    uint32_t tmp[4];
                    ldsm4t(tmp, stgB_u + (uint32_t)(st * 10240 * 2) +
                           (uint32_t)((ks * 136 + warp_n * 32 + np * 16) * 2) + bn_ld);
                    bf[2 * np][0]     = tmp[0]; bf[2 * np][1]     = tmp[2];
                    bf[2 * np + 1][0] = tmp[1]; bf[2 * np + 1][1] = tmp[3];
                }
#pragma unroll
                for (int mt = 0; mt < 4; mt++)
#pragma unroll
                    for (int nt = 0; nt < 4; nt++)
                        mma_f16(acc[mt][nt], af[mt], bf[nt]);
            }
            __syncthreads();
        }
#pragma unroll
        for (int mt = 0; mt < 4; mt++) {
#pragma unroll
            for (int half = 0; half < 2; half++) {
                int row = warp_m * 64 + mt * 16 + gq + half * 8;
#pragma unroll
                for (int nt = 0; nt < 4; nt++) {
#pragma unroll
                    for (int e = 0; e < 2; e++) {
                        int col = n0 + warp_n * 32 + nt * 8 + tq2 * 2 + e;
                        Tout[(size_t)row * HID_ + col] =
                            __float2half_rn(acc[mt][nt][half * 2 + e]);
                    }
                }
            }
        }
    }
#undef STG_A
#undef STG_B
}

// ---------------- tgt init ----------------
__global__ void init_tgt(const float* __restrict__ qe) {
    size_t i = (size_t)blockIdx.x * 256 + threadIdx.x;
    int c = (int)(i & 255);
    int q = (int)((i >> 8) & 15);
    float v = qe[q * HID_ + c];
    g_tgt[i] = v;
    g_tgt_h[i] = __float2half_rn(v);
}

// ---------------- self attention (reads combined qkv4, stride 1024) ----------------
__global__ __launch_bounds__(256) void self_attn() {
    int bn = blockIdx.x;
    __shared__ float sq[NQ_][260];
    __shared__ float sk[NQ_][260];
    __shared__ float sa[HEADS_][NQ_][NQ_ + 1];
    int t = threadIdx.x;
    const __half* base = g_qkv4_h + (size_t)bn * NQ_ * 1024;
    for (int i = t; i < NQ_ * HID_; i += 256) {
        int q = i >> 8, c = i & 255;
        sq[q][c] = __half2float(base[q * 1024 + c]);
        sk[q][c] = __half2float(base[q * 1024 + 256 + c]);
    }
    __syncthreads();
    const float scale = 0.17677669529663687f;
    for (int i = t; i < HEADS_ * NQ_ * NQ_; i += 256) {
        int h = i >> 8, q = (i >> 4) & 15, kk = i & 15;
        float acc = 0.0f;
#pragma unroll
        for (int d = 0; d < DH_; d++) acc += sq[q][h * DH_ + d] * sk[kk][h * DH_ + d];
        sa[h][q][kk] = acc * scale;
    }
    __syncthreads();
    if (t < HEADS_ * NQ_) {
        int h = t >> 4, q = t & 15;
        float m = -FLT_MAX;
#pragma unroll
        for (int kk = 0; kk < NQ_; kk++) m = fmaxf(m, sa[h][q][kk]);
        float s = 0.0f;
#pragma unroll
        for (int kk = 0; kk < NQ_; kk++) { float e = expf(sa[h][q][kk] - m); sa[h][q][kk] = e; s += e; }
        float inv = 1.0f / s;
#pragma unroll
        for (int kk = 0; kk < NQ_; kk++) sa[h][q][kk] *= inv;
    }
    __syncthreads();
    __half* out = g_ctx_h + (size_t)bn * NQ_ * HID_;
    for (int i = t; i < NQ_ * HID_; i += 256) {
        int q = i >> 8, c = i & 255;
        int h = c >> 5;
        float acc = 0.0f;
#pragma unroll
        for (int kk = 0; kk < NQ_; kk++)
            acc += sa[h][q][kk] * __half2float(base[kk * 1024 + 512 + c]);
        out[q * HID_ + c] = __float2half_rn(acc);
    }
}

// ---------------- cross-attn U = Q_h @ Wk_h (qc at offset 768 in qkv4) ----------------
__global__ __launch_bounds__(256) void cross_u(const float* __restrict__ Wk) {
    int h = blockIdx.x, bn = blockIdx.y;
    int c = threadIdx.x;
    __shared__ float sq[NQ_][DH_];
    for (int i = threadIdx.x; i < NQ_ * DH_; i += 256) {
        int q = i >> 5, d = i & 31;
        sq[q][d] = __half2float(
            g_qkv4_h[((size_t)bn * NQ_ + q) * 1024 + 768 + h * DH_ + d]);
    }
    __syncthreads();
    float acc[NQ_] = {};
#pragma unroll 4
    for (int d = 0; d < DH_; d++) {
        float w = Wk[(size_t)(h * DH_ + d) * HID_ + c];
#pragma unroll
        for (int q = 0; q < NQ_; q++) acc[q] += sq[q][d] * w;
    }
    __half* dst = g_uh + ((size_t)bn * 128 + h * NQ_) * HID_ + c;
#pragma unroll
    for (int q = 0; q < NQ_; q++) dst[(size_t)q * HID_] = __float2half_rn(acc[q]);
}

// ---------------- cross-attn output: ctx = T @ Wv_h^T + bv ----------------
__global__ __launch_bounds__(512) void cross_o(const float* __restrict__ Wv,
                                               const float* __restrict__ bv) {
    int h = blockIdx.x, bn = blockIdx.y;
    __shared__ float ws[DH_][HID_ + 1];
    int t = threadIdx.x;
    for (int i = t; i < DH_ * HID_; i += 512) {
        int d = i >> 8, c = i & 255;
        ws[d][c] = Wv[(size_t)(h * DH_ + d) * HID_ + c];
    }
    __syncthreads();
    int q = t >> 5, d = t & 31;
    const __half* trow = g_uh + ((size_t)bn * 128 + h * NQ_ + q) * HID_;
    float acc = 0.0f;
#pragma unroll 4
    for (int c = 0; c < HID_; c += 2) {
        __half2 hv = *reinterpret_cast<const __half2*>(trow + c);
        float2 f = __half22float2(hv);
        acc += f.x * ws[d][c] + f.y * ws[d][c + 1];
    }
    g_ctx_h[((size_t)bn * NQ_ + q) * HID_ + h * DH_ + d] = __float2half_rn(acc + bv[h * DH_ + d]);
}

// ---------------- final head ----------------
__global__ __launch_bounds__(256) void final_out(const float* __restrict__ W,
                                                 const float* __restrict__ bias,
                                                 float* __restrict__ out) {
    int row = blockIdx.x * 8 + (threadIdx.x >> 5);
    int lane = threadIdx.x & 31;
    const float* x = g_tgt + (size_t)row * HID_;
    float acc[4] = {};
#pragma unroll
    for (int i = 0; i < 8; i++) {
        int c = lane + i * 32;
        float xv = x[c];
#pragma unroll
        for (int j = 0; j < 4; j++) acc[j] += xv * W[j * HID_ + c];
    }
#pragma unroll
    for (int j = 0; j < 4; j++)
#pragma unroll
        for (int o = 16; o; o >>= 1) acc[j] += __shfl_xor_sync(0xffffffffu, acc[j], o);
    if (lane < 4) out[(size_t)row * 4 + lane] = acc[lane] + bias[lane];
}

// ---------------- host ----------------
extern "C" void kernel_launch(void* const* d_in, const int* in_sizes, int n_in,
                              void* d_out, int out_size) {
    (void)in_sizes; (void)n_in; (void)out_size;
    const float* img         = (const float*)d_in[0];
    const float* kp          = (const float*)d_in[1];
    const unsigned char* msk = (const unsigned char*)d_in[2];
    const float* proj_w      = (const float*)d_in[3];
    const float* proj_b      = (const float*)d_in[4];
    const float* query_embed = (const float*)d_in[5];
    const float* self_qkv_w  = (const float*)d_in[6];
    const float* self_qkv_b  = (const float*)d_in[7];
    const float* self_out_w  = (const float*)d_in[8];
    const float* self_out_b  = (const float*)d_in[9];
    const float* cross_qkv_w = (const float*)d_in[10];
    const float* cross_qkv_b = (const float*)d_in[11];
    const float* cross_out_w = (const float*)d_in[12];
    const float* cross_out_b = (const float*)d_in[13];
    const float* ffn1_w      = (const float*)d_in[14];
    const float* ffn1_b      = (const float*)d_in[15];
    const float* ffn2_w      = (const float*)d_in[16];
    const float* ffn2_b      = (const float*)d_in[17];
    const float* ln1_w       = (const float*)d_in[18];
    const float* ln1_b       = (const float*)d_in[19];
    const float* ln2_w       = (const float*)d_in[20];
    const float* ln2_b       = (const float*)d_in[21];
    const float* ln3_w       = (const float*)d_in[22];
    const float* ln3_b       = (const float*)d_in[23];
    const float* out_w       = (const float*)d_in[24];
    const float* out_b       = (const float*)d_in[25];
    float* out = (float*)d_out;

    float *tgt;
    unsigned char* valid;
    __half *feat_h, *mem_h, *tgt_h, *ctx_h, *qkv4_h, *uh, *ffn_h;
    __half *projw_h, *sout_h, *cout_h, *f1_h, *f2_h, *qkv4w_h;
    float *qkv4b;
    cudaGetSymbolAddress((void**)&tgt,   g_tgt);
    cudaGetSymbolAddress((void**)&valid, g_valid);
    cudaGetSymbolAddress((void**)&feat_h, g_feat_h);
    cudaGetSymbolAddress((void**)&mem_h,  g_mem_h);
    cudaGetSymbolAddress((void**)&tgt_h,  g_tgt_h);
    cudaGetSymbolAddress((void**)&ctx_h,  g_ctx_h);
    cudaGetSymbolAddress((void**)&qkv4_h, g_qkv4_h);
    cudaGetSymbolAddress((void**)&uh,     g_uh);
    cudaGetSymbolAddress((void**)&ffn_h,  g_ffn_h);
    cudaGetSymbolAddress((void**)&projw_h, g_projw_h);
    cudaGetSymbolAddress((void**)&sout_h,  g_sout_h);
    cudaGetSymbolAddress((void**)&cout_h,  g_cout_h);
    cudaGetSymbolAddress((void**)&f1_h,    g_f1_h);
    cudaGetSymbolAddress((void**)&f2_h,    g_f2_h);
    cudaGetSymbolAddress((void**)&qkv4w_h, g_qkv4w_h);
    cudaGetSymbolAddress((void**)&qkv4b,   g_qkv4b);

    cudaFuncSetAttribute((const void*)gemm_h<false>,
                         cudaFuncAttributeMaxDynamicSharedMemorySize, GEMM_SMEM_);
    cudaFuncSetAttribute((const void*)gemm_h<true>,
                         cudaFuncAttributeMaxDynamicSharedMemorySize, GEMM_SMEM_);
    cudaFuncSetAttribute((const void*)gemm_ln,
                         cudaFuncAttributeMaxDynamicSharedMemorySize, LN_SMEM_);
    cudaFuncSetAttribute((const void*)attn_fused,
                         cudaFuncAttributeMaxDynamicSharedMemorySize, ATTN_SMEM_);

    decode_mask<<<1, 512>>>(msk, valid);
    { dim3 g(128, 8, B_); transpose_img<<<g, 256>>>(img); }
    { dim3 g(P2_, N_KP, B_); roi_gather<<<g, C_>>>(kp); }

    f2h_all<<<(WT_ + 255) / 256, 256>>>(proj_w, self_out_w, cross_out_w, ffn1_w, ffn2_w);
    pack_qkv4<<<(3 * 1024 * 256 + 255) / 256, 256>>>(self_qkv_w, cross_qkv_w,
                                                     self_qkv_b, cross_qkv_b);

    // mem_h = fp16(feat @ proj_w^T + proj_b)
    gemm_h<false><<<dim3(2, 900), 256, GEMM_SMEM_>>>(
        feat_h, projw_h, proj_b, mem_h, MMEM_, HID_, C_, C_, C_, HID_);

    init_tgt<<<MROWS_, 256>>>(query_embed);

    for (int l = 0; l < DEPTH_; l++) {
        const __half* q4W = qkv4w_h + (size_t)l * 1024 * 256;
        const float*  q4B = qkv4b + l * 1024;
        const __half* soW = sout_h + (size_t)l * 65536;
        const float*  soB = self_out_b  + (size_t)l * HID_;
        const float*  cWf = cross_qkv_w + (size_t)l * 3 * HID_ * HID_;
        const float*  cB  = cross_qkv_b + (size_t)l * 3 * HID_;
        const __half* coW = cout_h + (size_t)l * 65536;
        const float*  coB = cross_out_b + (size_t)l * HID_;
        const __half* f1W = f1_h + (size_t)l * 262144;
        const float*  f1B = ffn1_b + (size_t)l * FFN_;
        const __half* f2W = f2_h + (size_t)l * 262144;
        const float*  f2B = ffn2_b + (size_t)l * HID_;

        // qkv + qc in one GEMM (N=1024)
        gemm_h<false><<<dim3(8, 64), 256, GEMM_SMEM_>>>(
            tgt_h, q4W, q4B, qkv4_h, MROWS_, 1024, HID_, HID_, HID_, 1024);
        self_attn<<<BN_, 256>>>();
        gemm_ln<<<128, 256, LN_SMEM_>>>(ctx_h, soW, soB, tgt,
                                        ln1_w + l * HID_, ln1_b + l * HID_, tgt, tgt_h, HID_);

        // cross attention (factored K/V)
        { dim3 g(HEADS_, BN_); cross_u<<<g, 256>>>(cWf + (size_t)HID_ * HID_); }
        attn_fused<<<BN_, 256, ATTN_SMEM_>>>();
        { dim3 g(HEADS_, BN_); cross_o<<<g, 512>>>(cWf + (size_t)2 * HID_ * HID_, cB + 2 * HID_); }
        gemm_ln<<<128, 256, LN_SMEM_>>>(ctx_h, coW, coB, tgt,
                                        ln2_w + l * HID_, ln2_b + l * HID_, tgt, tgt_h, HID_);

        // FFN
        gemm_h<true><<<dim3(8, 64), 256, GEMM_SMEM_>>>(
            tgt_h, f1W, f1B, ffn_h, MROWS_, FFN_, HID_, HID_, HID_, FFN_);
        gemm_ln<<<128, 256, LN_SMEM_>>>(ffn_h, f2W, f2B, tgt,
                                        ln3_w + l * HID_, ln3_b + l * HID_, tgt, tgt_h, FFN_);
    }

    final_out<<<MROWS_ / 8, 256>>>(out_w, out_b, out);
}